// round 12
// baseline (speedup 1.0000x reference)
#include <cuda_runtime.h>
#include <cstddef>
#include <cstdint>
#include <math.h>

#define DMODEL 1024
#define NTOK   4096
#define FFDIM  4096
#define SEQ    1024
#define REC_CTAS 128

__device__ float g_xn [NTOK*DMODEL];
__device__ float g_q  [NTOK*DMODEL];
__device__ float g_k  [NTOK*DMODEL];
__device__ float g_v  [NTOK*DMODEL];
__device__ float g_z  [NTOK*DMODEL];
__device__ float g_gm [NTOK*DMODEL];
__device__ float g_t1 [NTOK*128];
__device__ float g_h  [NTOK*DMODEL];
__device__ float g_att[NTOK*DMODEL];
__device__ float g_ao [NTOK*DMODEL];
__device__ float g_y  [NTOK*DMODEL];
__device__ float g_yn [NTOK*DMODEL];
__device__ float g_f1 [NTOK*FFDIM];
__device__ unsigned g_bar_count;
__device__ unsigned g_bar_sense;

// ---------------- helpers ----------------
__device__ __forceinline__ void mma_tf32(float* c,
    unsigned a0, unsigned a1, unsigned a2, unsigned a3,
    unsigned b0, unsigned b1)
{
    asm volatile("mma.sync.aligned.m16n8k8.row.col.f32.tf32.tf32.f32 "
                 "{%0,%1,%2,%3}, {%4,%5,%6,%7}, {%8,%9}, {%0,%1,%2,%3};\n"
                 : "+f"(c[0]), "+f"(c[1]), "+f"(c[2]), "+f"(c[3])
                 : "r"(a0), "r"(a1), "r"(a2), "r"(a3), "r"(b0), "r"(b1));
}

__device__ __forceinline__ float multi_reduce32(float (&acc)[32], int lane) {
#pragma unroll
    for (int d = 16; d >= 1; d >>= 1) {
        const bool up = (lane & d) != 0;
#pragma unroll
        for (int i = 0; i < d; i++) {
            float send = up ? acc[i] : acc[i + d];
            float recv = __shfl_xor_sync(0xffffffffu, send, d);
            float keep = up ? acc[i + d] : acc[i];
            acc[i] = keep + recv;
        }
    }
    return acc[0];
}

__device__ __forceinline__ float block_sum256(float v) {
    __shared__ float sred[9];
#pragma unroll
    for (int o = 16; o; o >>= 1) v += __shfl_xor_sync(0xffffffffu, v, o);
    int w = threadIdx.x >> 5, l = threadIdx.x & 31;
    if (l == 0) sred[w] = v;
    __syncthreads();
    if (threadIdx.x < 32) {
        float t = (l < 8) ? sred[l] : 0.f;
#pragma unroll
        for (int o = 4; o; o >>= 1) t += __shfl_xor_sync(0xffffffffu, t, o);
        if (l == 0) sred[8] = t;
    }
    __syncthreads();
    return sred[8];
}

__global__ __launch_bounds__(256)
void rmsnorm_kernel(const float* __restrict__ x, const float* __restrict__ w,
                    float* __restrict__ out) {
    const size_t base = (size_t)blockIdx.x * DMODEL;
    float vb[4]; float ss = 0.f;
#pragma unroll
    for (int i = 0; i < 4; i++) { float t = x[base + threadIdx.x + 256*i]; vb[i] = t; ss += t*t; }
    float inv = 1.f / (sqrtf(block_sum256(ss)) * 0.03125f + 1e-6f);
#pragma unroll
    for (int i = 0; i < 4; i++) { int c = threadIdx.x + 256*i; out[base + c] = w[c] * vb[i] * inv; }
}

__global__ __launch_bounds__(256)
void residual_norm_kernel(const float* __restrict__ x, const float* __restrict__ ao,
                          const float* __restrict__ hs, const float* __restrict__ w,
                          float* __restrict__ y, float* __restrict__ yn) {
    const size_t base = (size_t)blockIdx.x * DMODEL;
    float vb[4]; float ss = 0.f;
#pragma unroll
    for (int i = 0; i < 4; i++) {
        int c = threadIdx.x + 256*i;
        float t = x[base+c] + ao[base+c] + hs[base+c];
        vb[i] = t; y[base+c] = t; ss += t*t;
    }
    float inv = 1.f / (sqrtf(block_sum256(ss)) * 0.03125f + 1e-6f);
#pragma unroll
    for (int i = 0; i < 4; i++) { int c = threadIdx.x + 256*i; yn[base+c] = w[c] * vb[i] * inv; }
}

// ---------------- TF32 tensor-core GEMM — k-interleaved smem, LDS.64 frags ----
// C[M,N] = A[M,K] @ B[N,K]^T + bias. Block 128x128, BK=16, single sync per tile.
// SMEM row layout (20-float stride): within each 8-k group, k stored at position
// (k&3)*2 + (k>>2), so fragment pair (k, k+4) is adjacent -> one LDS.64.
#define TG_RS  20
#define TG_BUF (128*TG_RS)

// store 8 consecutive k values (r0 = k..k+3, r1 = k+4..k+7) interleaved
#define TG_ST8(dst, r0, r1) do {                                   \
    *(float2*)&(dst)[0] = make_float2((r0).x, (r1).x);             \
    *(float2*)&(dst)[2] = make_float2((r0).y, (r1).y);             \
    *(float2*)&(dst)[4] = make_float2((r0).z, (r1).z);             \
    *(float2*)&(dst)[6] = make_float2((r0).w, (r1).w); } while (0)

template<int EPI>
__device__ __forceinline__
void tgemm_body(const float* __restrict__ A, const float* __restrict__ B,
                const float* __restrict__ bias, const float* __restrict__ res,
                float* __restrict__ C, int N, int K,
                float* As, float* Bs, int bm, int bn)
{
    const int tid = threadIdx.x;
    const int wid = tid >> 5, lane = tid & 31;
    const int gq = lane >> 2, tq = lane & 3;
    const int m0 = (wid & 1) * 64, n0 = (wid >> 1) * 32;

    const int crow = tid >> 1;          // tile row this thread fills
    const int ck   = (tid & 1) * 8;     // k-group (0 or 8)
    const float* Ap = A + (size_t)(bm + crow) * K + ck;
    const float* Bp = B + (size_t)(bn + crow) * K + ck;
    float* asw = As + crow * TG_RS + ck;
    float* bsw = Bs + crow * TG_RS + ck;

    float acc[4][4][4];
#pragma unroll
    for (int i = 0; i < 4; i++)
#pragma unroll
        for (int j = 0; j < 4; j++)
#pragma unroll
            for (int e = 0; e < 4; e++) acc[i][j][e] = 0.f;

    float4 ra0 = *(const float4*)(Ap);
    float4 ra1 = *(const float4*)(Ap + 4);
    float4 rb0 = *(const float4*)(Bp);
    float4 rb1 = *(const float4*)(Bp + 4);
    TG_ST8(asw, ra0, ra1);
    TG_ST8(bsw, rb0, rb1);
    __syncthreads();

    int buf = 0;
    for (int kt = 0; kt < K; kt += 16) {
        const bool more = (kt + 16) < K;
        if (more) {
            ra0 = *(const float4*)(Ap + kt + 16);
            ra1 = *(const float4*)(Ap + kt + 16 + 4);
            rb0 = *(const float4*)(Bp + kt + 16);
            rb1 = *(const float4*)(Bp + kt + 16 + 4);
        }
        const float* Asb = As + buf * TG_BUF;
        const float* Bsb = Bs + buf * TG_BUF;
#pragma unroll
        for (int kb = 0; kb < 16; kb += 8) {
            unsigned bf[4][2];
#pragma unroll
            for (int j = 0; j < 4; j++) {
                const float2 bv = *(const float2*)&Bsb[(n0 + j*8 + gq)*TG_RS + kb + 2*tq];
                bf[j][0] = __float_as_uint(bv.x);
                bf[j][1] = __float_as_uint(bv.y);
            }
#pragma unroll
            for (int i = 0; i < 4; i++) {
                const int r = m0 + i*16 + gq;
                const float2 alo = *(const float2*)&Asb[(r    )*TG_RS + kb + 2*tq];
                const float2 ahi = *(const float2*)&Asb[(r + 8)*TG_RS + kb + 2*tq];
                const unsigned a0 = __float_as_uint(alo.x);
                const unsigned a1 = __float_as_uint(ahi.x);
                const unsigned a2 = __float_as_uint(alo.y);
                const unsigned a3 = __float_as_uint(ahi.y);
#pragma unroll
                for (int j = 0; j < 4; j++)
                    mma_tf32(acc[i][j], a0, a1, a2, a3, bf[j][0], bf[j][1]);
            }
        }
        if (more) {
            float* ad = asw + (buf ^ 1) * TG_BUF;
            float* bd = bsw + (buf ^ 1) * TG_BUF;
            TG_ST8(ad, ra0, ra1);      // buf^1 fully consumed before prior sync
            TG_ST8(bd, rb0, rb1);
            __syncthreads();
            buf ^= 1;
        }
    }

#pragma unroll
    for (int i = 0; i < 4; i++) {
#pragma unroll
        for (int half = 0; half < 2; half++) {
            const int gr = bm + m0 + i*16 + gq + half*8;
            float* crowp = C + (size_t)gr * N;
            const float* rrow = res ? res + (size_t)gr * N : nullptr;
#pragma unroll
            for (int j = 0; j < 4; j++) {
                const int gc = bn + n0 + j*8 + tq*2;
#pragma unroll
                for (int e = 0; e < 2; e++) {
                    float vv = acc[i][j][half*2 + e] + bias[gc + e];
                    if (EPI == 1) vv = fmaxf(vv, 0.f);
                    else if (EPI == 2) {
                        vv = 1.f / (1.f + __expf(-vv));
                        vv = fminf(fmaxf(vv, 1e-6f), 1.f - 1e-6f);
                    } else if (EPI == 3) {
                        float u = 0.7978845608028654f * (vv + 0.044715f * vv * vv * vv);
                        vv = 0.5f * vv * (1.f + tanhf(u));
                    }
                    if (rrow) vv += rrow[gc + e];
                    crowp[gc + e] = vv;
                }
            }
        }
    }
}

template<int EPI>
__global__ __launch_bounds__(256, 2)
void tgemm_kernel(const float* __restrict__ A, const float* __restrict__ B,
                  const float* __restrict__ bias, const float* __restrict__ res,
                  float* __restrict__ C, int M, int N, int K)
{
    __shared__ float As[2*TG_BUF];
    __shared__ float Bs[2*TG_BUF];
    tgemm_body<EPI>(A, B, bias, res, C, N, K, As, Bs,
                    blockIdx.y * 128, blockIdx.x * 128);
}

struct Ptr3 { const float* B; const float* bias; float* C; };
struct Quad { Ptr3 p[4]; };

__global__ __launch_bounds__(256, 2)
void tgemm4_kernel(const float* __restrict__ A, Quad q, int N, int K)
{
    __shared__ float As[2*TG_BUF];
    __shared__ float Bs[2*TG_BUF];
    Ptr3 pr = q.p[blockIdx.z];
    tgemm_body<0>(A, pr.B, pr.bias, nullptr, pr.C, N, K, As, Bs,
                  blockIdx.y * 128, blockIdx.x * 128);
}

// ---------------- persistent recurrence (known-good) ----------------
__global__ __launch_bounds__(256, 1)
void recurrence_kernel(const float* __restrict__ z, const float* __restrict__ gm,
                       const float* __restrict__ Wg, const float* __restrict__ bg,
                       float* __restrict__ hs)
{
    const int tid = threadIdx.x, w = tid >> 5, l = tid & 31;
    const int blk = blockIdx.x;
    const int k0 = w * 128 + l * 4;
    float4 wv[8];
#pragma unroll
    for (int r = 0; r < 8; r++)
        wv[r] = *(const float4*)(Wg + (size_t)(blk*8 + r) * DMODEL + k0);

    __shared__ float red[256];
    float bgv = 0.f, hprev = 0.f; int jout = 0, bout = 0;
    if (tid < 32) { jout = blk*8 + (tid >> 2); bout = tid & 3; bgv = bg[jout]; }

    for (int t = 0; t < SEQ; t++) {
        float acc[32];
#pragma unroll
        for (int a = 0; a < 32; a++) acc[a] = 0.f;
        if (t > 0) {
#pragma unroll
            for (int b = 0; b < 4; b++) {
                float4 hv = __ldcg((const float4*)(hs + ((size_t)b*SEQ + (t-1))*DMODEL + k0));
#pragma unroll
                for (int r = 0; r < 8; r++) {
                    acc[r*4+b] = fmaf(wv[r].x, hv.x, acc[r*4+b]);
                    acc[r*4+b] = fmaf(wv[r].y, hv.y, acc[r*4+b]);
                    acc[r*4+b] = fmaf(wv[r].z, hv.z, acc[r*4+b]);
                    acc[r*4+b] = fmaf(wv[r].w, hv.w, acc[r*4+b]);
                }
            }
        }
        float part = multi_reduce32(acc, l);
        red[w*32 + l] = part;
        __syncthreads();
        if (tid < 32) {
            float sum = bgv;
#pragma unroll
            for (int ww = 0; ww < 8; ww++) sum += red[ww*32 + tid];
            float sig = 1.f / (1.f + __expf(-sum));
            size_t base = ((size_t)bout * SEQ + t) * DMODEL + jout;
            hprev = z[base] * sig + gm[base] * hprev;
            hs[base] = hprev;
            __threadfence();
        }
        __syncthreads();
        if (tid == 0) {
            unsigned sv = *(volatile unsigned*)&g_bar_sense;
            unsigned prev = atomicAdd(&g_bar_count, 1u);
            if (prev == REC_CTAS - 1) {
                g_bar_count = 0;
                __threadfence();
                atomicExch(&g_bar_sense, sv ^ 1u);
            } else {
                while (*(volatile unsigned*)&g_bar_sense == sv) { }
            }
            __threadfence();
        }
        __syncthreads();
    }
}

// ---------------- fused attention (butterfly PV + register prefetch) ----------
__global__ __launch_bounds__(256)
void attn_kernel(const float* __restrict__ q, const float* __restrict__ k,
                 const float* __restrict__ v, float* __restrict__ ao)
{
    const int qb = blockIdx.x & 127;
    const int bh = blockIdx.x >> 7;
    const int b = bh >> 4, h = bh & 15;
    __shared__ float Qs[8][64];
    __shared__ float Ts[64*65];
    const int tid = threadIdx.x, w = tid >> 5, l = tid & 31;
    const size_t bbase = (size_t)b * SEQ * DMODEL + (size_t)h * 64;
    const int qrow0 = qb * 8;

    const int pr_r  = tid >> 4;
    const int pr_c4 = (tid & 15) * 4;

    if (tid < 128) {
        int r = tid >> 4, c4 = (tid & 15) * 4;
        float4 t = *(const float4*)(q + bbase + (size_t)(qrow0 + r) * DMODEL + c4);
        Qs[r][c4] = t.x; Qs[r][c4+1] = t.y; Qs[r][c4+2] = t.z; Qs[r][c4+3] = t.w;
    }

    float4 pf[4];
#pragma unroll
    for (int it = 0; it < 4; it++)
        pf[it] = *(const float4*)(k + bbase + (size_t)(pr_r + it*16) * DMODEL + pr_c4);

    float p[32];
#pragma unroll 1
    for (int j = 0; j < 16; j++) {
        __syncthreads();
#pragma unroll
        for (int it = 0; it < 4; it++) {
            float* dst = &Ts[(pr_r + it*16)*65 + pr_c4];
            dst[0]=pf[it].x; dst[1]=pf[it].y; dst[2]=pf[it].z; dst[3]=pf[it].w;
        }
        __syncthreads();
        if (j < 15) {
#pragma unroll
            for (int it = 0; it < 4; it++)
                pf[it] = *(const float4*)(k + bbase + (size_t)((j+1)*64 + pr_r + it*16) * DMODEL + pr_c4);
        }
#pragma unroll
        for (int ii = 0; ii < 2; ii++) {
            const int kr = l + 32*ii;
            float s = 0.f;
#pragma unroll
            for (int d = 0; d < 64; d++) s = fmaf(Qs[w][d], Ts[kr*65 + d], s);
            p[2*j + ii] = s * 0.125f;
        }
    }

#pragma unroll
    for (int it = 0; it < 4; it++)
        pf[it] = *(const float4*)(v + bbase + (size_t)(pr_r + it*16) * DMODEL + pr_c4);

    float m = -3.0e38f;
#pragma unroll
    for (int i = 0; i < 32; i++) m = fmaxf(m, p[i]);
#pragma unroll
    for (int o = 16; o; o >>= 1) m = fmaxf(m, __shfl_xor_sync(0xffffffffu, m, o));
    float s = 0.f;
#pragma unroll
    for (int i = 0; i < 32; i++) { p[i] = __expf(p[i] - m); s += p[i]; }
#pragma unroll
    for (int o = 16; o; o >>= 1) s += __shfl_xor_sync(0xffffffffu, s, o);
    float inv = 1.f / s;
#pragma unroll
    for (int i = 0; i < 32; i++) p[i] *= inv;

    float o0[32], o1[32];
#pragma unroll
    for (int i = 0; i < 32; i++) { o0[i] = 0.f; o1[i] = 0.f; }
#pragma unroll 1
    for (int j = 0; j < 16; j++) {
        __syncthreads();
#pragma unroll
        for (int it = 0; it < 4; it++) {
            float* dst = &Ts[(pr_r + it*16)*65 + pr_c4];
            dst[0]=pf[it].x; dst[1]=pf[it].y; dst[2]=pf[it].z; dst[3]=pf[it].w;
        }
        __syncthreads();
        if (j < 15) {
#pragma unroll
            for (int it = 0; it < 4; it++)
                pf[it] = *(const float4*)(v + bbase + (size_t)((j+1)*64 + pr_r + it*16) * DMODEL + pr_c4);
        }
#pragma unroll
        for (int ii = 0; ii < 2; ii++) {
            const int kr = l + 32*ii;
            const float pi = p[2*j + ii];
#pragma unroll
            for (int d = 0; d < 32; d++) o0[d] = fmaf(pi, Ts[kr*65 + d],      o0[d]);
#pragma unroll
            for (int d = 0; d < 32; d++) o1[d] = fmaf(pi, Ts[kr*65 + 32 + d], o1[d]);
        }
    }
    float r0 = multi_reduce32(o0, l);
    float r1 = multi_reduce32(o1, l);
    size_t ob = bbase + (size_t)(qrow0 + w) * DMODEL;
    ao[ob + l] = r0;
    ao[ob + 32 + l] = r1;
}

extern "C" void kernel_launch(void* const* d_in, const int* in_sizes, int n_in,
                              void* d_out, int out_size)
{
    (void)in_sizes; (void)n_in; (void)out_size;
    const float* x   = (const float*)d_in[0];
    const float* n1w = (const float*)d_in[1];
    const float* Wq  = (const float*)d_in[2];  const float* bq = (const float*)d_in[3];
    const float* Wk  = (const float*)d_in[4];  const float* bk = (const float*)d_in[5];
    const float* Wv  = (const float*)d_in[6];  const float* bv = (const float*)d_in[7];
    const float* Wz  = (const float*)d_in[8];  const float* bz = (const float*)d_in[9];
    const float* Wg  = (const float*)d_in[10]; const float* bg = (const float*)d_in[11];
    const float* gdw = (const float*)d_in[12]; const float* gdb= (const float*)d_in[13];
    const float* guw = (const float*)d_in[14]; const float* gub= (const float*)d_in[15];
    const float* Wo  = (const float*)d_in[16]; const float* bo = (const float*)d_in[17];
    const float* n2w = (const float*)d_in[18];
    const float* f1w = (const float*)d_in[19]; const float* f1b= (const float*)d_in[20];
    const float* f2w = (const float*)d_in[21]; const float* f2b= (const float*)d_in[22];
    float* out = (float*)d_out;

    float *xn, *qp, *kp, *vp, *zp, *gmp, *t1, *hp, *attp, *aop, *yp, *ynp, *f1p;
    cudaGetSymbolAddress((void**)&xn,  g_xn);
    cudaGetSymbolAddress((void**)&qp,  g_q);
    cudaGetSymbolAddress((void**)&kp,  g_k);
    cudaGetSymbolAddress((void**)&vp,  g_v);
    cudaGetSymbolAddress((void**)&zp,  g_z);
    cudaGetSymbolAddress((void**)&gmp, g_gm);
    cudaGetSymbolAddress((void**)&t1,  g_t1);
    cudaGetSymbolAddress((void**)&hp,  g_h);
    cudaGetSymbolAddress((void**)&attp,g_att);
    cudaGetSymbolAddress((void**)&aop, g_ao);
    cudaGetSymbolAddress((void**)&yp,  g_y);
    cudaGetSymbolAddress((void**)&ynp, g_yn);
    cudaGetSymbolAddress((void**)&f1p, g_f1);

    // 1. rmsnorm
    rmsnorm_kernel<<<NTOK, 256>>>(x, n1w, xn);
    // 2. Q/K/V/Z projections fused into one launch
    Quad quad;
    quad.p[0] = {Wq, bq, qp};
    quad.p[1] = {Wk, bk, kp};
    quad.p[2] = {Wv, bv, vp};
    quad.p[3] = {Wz, bz, zp};
    tgemm4_kernel<<<dim3(DMODEL/128, NTOK/128, 4), 256>>>(xn, quad, DMODEL, DMODEL);
    // 3. gamma MLP
    tgemm_kernel<1><<<dim3(1, NTOK/128), 256>>>(zp, gdw, gdb, nullptr, t1, NTOK, 128, DMODEL);
    tgemm_kernel<2><<<dim3(DMODEL/128, NTOK/128), 256>>>(t1, guw, gub, nullptr, gmp, NTOK, DMODEL, 128);
    // 4. recurrence
    recurrence_kernel<<<REC_CTAS, 256>>>(zp, gmp, Wg, bg, hp);
    // 5. attention + Wo
    attn_kernel<<<4*16*128, 256>>>(qp, kp, vp, attp);
    tgemm_kernel<0><<<dim3(DMODEL/128, NTOK/128), 256>>>(attp, Wo, bo, nullptr, aop, NTOK, DMODEL, DMODEL);
    // 6-7. residual + norm2, FFN, final residual (-> d_out)
    residual_norm_kernel<<<NTOK, 256>>>(x, aop, hp, n2w, yp, ynp);
    tgemm_kernel<3><<<dim3(FFDIM/128, NTOK/128), 256>>>(ynp, f1w, f1b, nullptr, f1p, NTOK, FFDIM, DMODEL);
    tgemm_kernel<0><<<dim3(DMODEL/128, NTOK/128), 256>>>(f1p, f2w, f2b, yp, out, NTOK, DMODEL, FFDIM);
}

// round 13
// speedup vs baseline: 1.0953x; 1.0953x over previous
#include <cuda_runtime.h>
#include <cstddef>
#include <cstdint>
#include <math.h>

#define DMODEL 1024
#define NTOK   4096
#define FFDIM  4096
#define SEQ    1024
#define REC_CTAS 128

__device__ float g_xn [NTOK*DMODEL];
__device__ float g_q  [NTOK*DMODEL];
__device__ float g_k  [NTOK*DMODEL];
__device__ float g_v  [NTOK*DMODEL];
__device__ float g_z  [NTOK*DMODEL];
__device__ float g_gm [NTOK*DMODEL];
__device__ float g_t1 [NTOK*128];
__device__ float g_h  [NTOK*DMODEL];
__device__ float g_att[NTOK*DMODEL];
__device__ float g_ao [NTOK*DMODEL];
__device__ float g_y  [NTOK*DMODEL];
__device__ float g_yn [NTOK*DMODEL];
__device__ float g_f1 [NTOK*FFDIM];
__device__ unsigned g_bar_count;
__device__ unsigned g_bar_sense;

// ---------------- helpers ----------------
__device__ __forceinline__ void mma_tf32(float* c,
    unsigned a0, unsigned a1, unsigned a2, unsigned a3,
    unsigned b0, unsigned b1)
{
    asm volatile("mma.sync.aligned.m16n8k8.row.col.f32.tf32.tf32.f32 "
                 "{%0,%1,%2,%3}, {%4,%5,%6,%7}, {%8,%9}, {%0,%1,%2,%3};\n"
                 : "+f"(c[0]), "+f"(c[1]), "+f"(c[2]), "+f"(c[3])
                 : "r"(a0), "r"(a1), "r"(a2), "r"(a3), "r"(b0), "r"(b1));
}

__device__ __forceinline__ void cp_async16(uint32_t dst_smem, const void* src) {
    asm volatile("cp.async.cg.shared.global [%0], [%1], 16;"
                 :: "r"(dst_smem), "l"(src));
}
__device__ __forceinline__ void cp_commit() {
    asm volatile("cp.async.commit_group;");
}

__device__ __forceinline__ float multi_reduce32(float (&acc)[32], int lane) {
#pragma unroll
    for (int d = 16; d >= 1; d >>= 1) {
        const bool up = (lane & d) != 0;
#pragma unroll
        for (int i = 0; i < d; i++) {
            float send = up ? acc[i] : acc[i + d];
            float recv = __shfl_xor_sync(0xffffffffu, send, d);
            float keep = up ? acc[i + d] : acc[i];
            acc[i] = keep + recv;
        }
    }
    return acc[0];
}

__device__ __forceinline__ float block_sum256(float v) {
    __shared__ float sred[9];
#pragma unroll
    for (int o = 16; o; o >>= 1) v += __shfl_xor_sync(0xffffffffu, v, o);
    int w = threadIdx.x >> 5, l = threadIdx.x & 31;
    if (l == 0) sred[w] = v;
    __syncthreads();
    if (threadIdx.x < 32) {
        float t = (l < 8) ? sred[l] : 0.f;
#pragma unroll
        for (int o = 4; o; o >>= 1) t += __shfl_xor_sync(0xffffffffu, t, o);
        if (l == 0) sred[8] = t;
    }
    __syncthreads();
    return sred[8];
}

__global__ __launch_bounds__(256)
void rmsnorm_kernel(const float* __restrict__ x, const float* __restrict__ w,
                    float* __restrict__ out) {
    const size_t base = (size_t)blockIdx.x * DMODEL;
    float vb[4]; float ss = 0.f;
#pragma unroll
    for (int i = 0; i < 4; i++) { float t = x[base + threadIdx.x + 256*i]; vb[i] = t; ss += t*t; }
    float inv = 1.f / (sqrtf(block_sum256(ss)) * 0.03125f + 1e-6f);
#pragma unroll
    for (int i = 0; i < 4; i++) { int c = threadIdx.x + 256*i; out[base + c] = w[c] * vb[i] * inv; }
}

__global__ __launch_bounds__(256)
void residual_norm_kernel(const float* __restrict__ x, const float* __restrict__ ao,
                          const float* __restrict__ hs, const float* __restrict__ w,
                          float* __restrict__ y, float* __restrict__ yn) {
    const size_t base = (size_t)blockIdx.x * DMODEL;
    float vb[4]; float ss = 0.f;
#pragma unroll
    for (int i = 0; i < 4; i++) {
        int c = threadIdx.x + 256*i;
        float t = x[base+c] + ao[base+c] + hs[base+c];
        vb[i] = t; y[base+c] = t; ss += t*t;
    }
    float inv = 1.f / (sqrtf(block_sum256(ss)) * 0.03125f + 1e-6f);
#pragma unroll
    for (int i = 0; i < 4; i++) { int c = threadIdx.x + 256*i; yn[base+c] = w[c] * vb[i] * inv; }
}

// ---------------- TF32 tensor-core GEMM (R10 exact: 3-stage cp.async ring) ----
#define TG_BK 16
#define TG_RS 20
#define TG_STAGE (128*TG_RS)
#define TG_SMEM_BYTES (2*3*TG_STAGE*4)

template<int EPI>
__device__ __forceinline__
void tgemm_body(const float* __restrict__ A, const float* __restrict__ B,
                const float* __restrict__ bias, const float* __restrict__ res,
                float* __restrict__ C, int N, int K,
                float* As, float* Bs, int bm, int bn)
{
    const int tid = threadIdx.x;
    const int wid = tid >> 5, lane = tid & 31;
    const int gq = lane >> 2, tq = lane & 3;
    const int m0 = (wid & 1) * 64, n0 = (wid >> 1) * 32;

    const int crow = tid >> 1;
    const int ck  = (tid & 1) * 8;
    const float* Ap = A + (size_t)(bm + crow) * K + ck;
    const float* Bp = B + (size_t)(bn + crow) * K + ck;

    uint32_t aSt[3], bSt[3];
#pragma unroll
    for (int st = 0; st < 3; st++) {
        aSt[st] = (uint32_t)__cvta_generic_to_shared(&As[st*TG_STAGE + crow*TG_RS + ck]);
        bSt[st] = (uint32_t)__cvta_generic_to_shared(&Bs[st*TG_STAGE + crow*TG_RS + ck]);
    }

    float acc[4][4][4];
#pragma unroll
    for (int i = 0; i < 4; i++)
#pragma unroll
        for (int j = 0; j < 4; j++)
#pragma unroll
            for (int e = 0; e < 4; e++) acc[i][j][e] = 0.f;

    cp_async16(aSt[0],      Ap);     cp_async16(aSt[0] + 16, Ap + 4);
    cp_async16(bSt[0],      Bp);     cp_async16(bSt[0] + 16, Bp + 4);
    cp_commit();
    if (TG_BK < K) {
        cp_async16(aSt[1],      Ap + TG_BK);     cp_async16(aSt[1] + 16, Ap + TG_BK + 4);
        cp_async16(bSt[1],      Bp + TG_BK);     cp_async16(bSt[1] + 16, Bp + TG_BK + 4);
    }
    cp_commit();

    int s = 0, s2 = 2;
    for (int kt = 0; kt < K; kt += TG_BK) {
        asm volatile("cp.async.wait_group 1;");
        __syncthreads();
        if (kt + 2*TG_BK < K) {
            const float* An = Ap + kt + 2*TG_BK;
            const float* Bn = Bp + kt + 2*TG_BK;
            cp_async16(aSt[s2],      An);     cp_async16(aSt[s2] + 16, An + 4);
            cp_async16(bSt[s2],      Bn);     cp_async16(bSt[s2] + 16, Bn + 4);
        }
        cp_commit();

        const float* Asb = As + s*TG_STAGE;
        const float* Bsb = Bs + s*TG_STAGE;
#pragma unroll
        for (int kb = 0; kb < TG_BK; kb += 8) {
            unsigned bf[4][2];
#pragma unroll
            for (int j = 0; j < 4; j++) {
                const int n = n0 + j*8 + gq;
                bf[j][0] = __float_as_uint(Bsb[n*TG_RS + kb+tq]);
                bf[j][1] = __float_as_uint(Bsb[n*TG_RS + kb+tq+4]);
            }
#pragma unroll
            for (int i = 0; i < 4; i++) {
                const int r = m0 + i*16 + gq;
                unsigned a0 = __float_as_uint(Asb[(r  )*TG_RS + kb+tq]);
                unsigned a1 = __float_as_uint(Asb[(r+8)*TG_RS + kb+tq]);
                unsigned a2 = __float_as_uint(Asb[(r  )*TG_RS + kb+tq+4]);
                unsigned a3 = __float_as_uint(Asb[(r+8)*TG_RS + kb+tq+4]);
#pragma unroll
                for (int j = 0; j < 4; j++)
                    mma_tf32(acc[i][j], a0, a1, a2, a3, bf[j][0], bf[j][1]);
            }
        }
        s  = (s  == 2) ? 0 : s  + 1;
        s2 = (s2 == 2) ? 0 : s2 + 1;
    }

#pragma unroll
    for (int i = 0; i < 4; i++) {
#pragma unroll
        for (int half = 0; half < 2; half++) {
            const int gr = bm + m0 + i*16 + gq + half*8;
            float* crowp = C + (size_t)gr * N;
            const float* rrow = res ? res + (size_t)gr * N : nullptr;
#pragma unroll
            for (int j = 0; j < 4; j++) {
                const int gc = bn + n0 + j*8 + tq*2;
#pragma unroll
                for (int e = 0; e < 2; e++) {
                    float vv = acc[i][j][half*2 + e] + bias[gc + e];
                    if (EPI == 1) vv = fmaxf(vv, 0.f);
                    else if (EPI == 2) {
                        vv = 1.f / (1.f + __expf(-vv));
                        vv = fminf(fmaxf(vv, 1e-6f), 1.f - 1e-6f);
                    } else if (EPI == 3) {
                        float u = 0.7978845608028654f * (vv + 0.044715f * vv * vv * vv);
                        vv = 0.5f * vv * (1.f + tanhf(u));
                    }
                    if (rrow) vv += rrow[gc + e];
                    crowp[gc + e] = vv;
                }
            }
        }
    }
}

template<int EPI>
__global__ __launch_bounds__(256, 2)
void tgemm_kernel(const float* __restrict__ A, const float* __restrict__ B,
                  const float* __restrict__ bias, const float* __restrict__ res,
                  float* __restrict__ C, int M, int N, int K)
{
    extern __shared__ float dsm[];
    tgemm_body<EPI>(A, B, bias, res, C, N, K, dsm, dsm + 3*TG_STAGE,
                    blockIdx.y * 128, blockIdx.x * 128);
}

struct Ptr3 { const float* B; const float* bias; float* C; };
struct Quad { Ptr3 p[4]; };

__global__ __launch_bounds__(256, 2)
void tgemm4_kernel(const float* __restrict__ A, Quad q, int N, int K)
{
    extern __shared__ float dsm[];
    Ptr3 pr = q.p[blockIdx.z];
    tgemm_body<0>(A, pr.B, pr.bias, nullptr, pr.C, N, K, dsm, dsm + 3*TG_STAGE,
                  blockIdx.y * 128, blockIdx.x * 128);
}

// ---------------- persistent recurrence (known-good) ----------------
__global__ __launch_bounds__(256, 1)
void recurrence_kernel(const float* __restrict__ z, const float* __restrict__ gm,
                       const float* __restrict__ Wg, const float* __restrict__ bg,
                       float* __restrict__ hs)
{
    const int tid = threadIdx.x, w = tid >> 5, l = tid & 31;
    const int blk = blockIdx.x;
    const int k0 = w * 128 + l * 4;
    float4 wv[8];
#pragma unroll
    for (int r = 0; r < 8; r++)
        wv[r] = *(const float4*)(Wg + (size_t)(blk*8 + r) * DMODEL + k0);

    __shared__ float red[256];
    float bgv = 0.f, hprev = 0.f; int jout = 0, bout = 0;
    if (tid < 32) { jout = blk*8 + (tid >> 2); bout = tid & 3; bgv = bg[jout]; }

    for (int t = 0; t < SEQ; t++) {
        float acc[32];
#pragma unroll
        for (int a = 0; a < 32; a++) acc[a] = 0.f;
        if (t > 0) {
#pragma unroll
            for (int b = 0; b < 4; b++) {
                float4 hv = __ldcg((const float4*)(hs + ((size_t)b*SEQ + (t-1))*DMODEL + k0));
#pragma unroll
                for (int r = 0; r < 8; r++) {
                    acc[r*4+b] = fmaf(wv[r].x, hv.x, acc[r*4+b]);
                    acc[r*4+b] = fmaf(wv[r].y, hv.y, acc[r*4+b]);
                    acc[r*4+b] = fmaf(wv[r].z, hv.z, acc[r*4+b]);
                    acc[r*4+b] = fmaf(wv[r].w, hv.w, acc[r*4+b]);
                }
            }
        }
        float part = multi_reduce32(acc, l);
        red[w*32 + l] = part;
        __syncthreads();
        if (tid < 32) {
            float sum = bgv;
#pragma unroll
            for (int ww = 0; ww < 8; ww++) sum += red[ww*32 + tid];
            float sig = 1.f / (1.f + __expf(-sum));
            size_t base = ((size_t)bout * SEQ + t) * DMODEL + jout;
            hprev = z[base] * sig + gm[base] * hprev;
            hs[base] = hprev;
            __threadfence();
        }
        __syncthreads();
        if (tid == 0) {
            unsigned sv = *(volatile unsigned*)&g_bar_sense;
            unsigned prev = atomicAdd(&g_bar_count, 1u);
            if (prev == REC_CTAS - 1) {
                g_bar_count = 0;
                __threadfence();
                atomicExch(&g_bar_sense, sv ^ 1u);
            } else {
                while (*(volatile unsigned*)&g_bar_sense == sv) { }
            }
            __threadfence();
        }
        __syncthreads();
    }
}

// ---------------- fused attention: vectorized LDS.128 smem streams ------------
// Ts stride 68 floats (17*4): float4-aligned rows; per 8-lane phase the quad
// index 17*l mod 8 covers all 8 bank-quads -> conflict-free LDS.128/STS.128.
#define AT_TS 68

__global__ __launch_bounds__(256)
void attn_kernel(const float* __restrict__ q, const float* __restrict__ k,
                 const float* __restrict__ v, float* __restrict__ ao)
{
    const int qb = blockIdx.x & 127;
    const int bh = blockIdx.x >> 7;
    const int b = bh >> 4, h = bh & 15;
    __shared__ float Qs[8][64];
    __shared__ float Ts[64*AT_TS];
    const int tid = threadIdx.x, w = tid >> 5, l = tid & 31;
    const size_t bbase = (size_t)b * SEQ * DMODEL + (size_t)h * 64;
    const int qrow0 = qb * 8;

    const int pr_r  = tid >> 4;
    const int pr_c4 = (tid & 15) * 4;

    if (tid < 128) {
        int r = tid >> 4, c4 = (tid & 15) * 4;
        float4 t = *(const float4*)(q + bbase + (size_t)(qrow0 + r) * DMODEL + c4);
        *(float4*)&Qs[r][c4] = t;
    }

    float4 pf[4];
#pragma unroll
    for (int it = 0; it < 4; it++)
        pf[it] = *(const float4*)(k + bbase + (size_t)(pr_r + it*16) * DMODEL + pr_c4);

    __syncthreads();                 // Qs visible
    float4 qreg[16];                 // warp's Q row, register-resident
#pragma unroll
    for (int i = 0; i < 16; i++) qreg[i] = *(const float4*)&Qs[w][i*4];

    float p[32];
#pragma unroll 1
    for (int j = 0; j < 16; j++) {
        __syncthreads();             // prior tile compute done -> Ts free
#pragma unroll
        for (int it = 0; it < 4; it++)
            *(float4*)&Ts[(pr_r + it*16)*AT_TS + pr_c4] = pf[it];
        __syncthreads();
        if (j < 15) {
#pragma unroll
            for (int it = 0; it < 4; it++)
                pf[it] = *(const float4*)(k + bbase + (size_t)((j+1)*64 + pr_r + it*16) * DMODEL + pr_c4);
        }
#pragma unroll
        for (int ii = 0; ii < 2; ii++) {
            const int kr = l + 32*ii;
            const float4* trow = (const float4*)&Ts[kr*AT_TS];
            float s = 0.f;
#pragma unroll
            for (int i = 0; i < 16; i++) {
                float4 tv = trow[i];
                s = fmaf(qreg[i].x, tv.x, s);
                s = fmaf(qreg[i].y, tv.y, s);
                s = fmaf(qreg[i].z, tv.z, s);
                s = fmaf(qreg[i].w, tv.w, s);
            }
            p[2*j + ii] = s * 0.125f;
        }
    }

#pragma unroll
    for (int it = 0; it < 4; it++)
        pf[it] = *(const float4*)(v + bbase + (size_t)(pr_r + it*16) * DMODEL + pr_c4);

    float m = -3.0e38f;
#pragma unroll
    for (int i = 0; i < 32; i++) m = fmaxf(m, p[i]);
#pragma unroll
    for (int o = 16; o; o >>= 1) m = fmaxf(m, __shfl_xor_sync(0xffffffffu, m, o));
    float s = 0.f;
#pragma unroll
    for (int i = 0; i < 32; i++) { p[i] = __expf(p[i] - m); s += p[i]; }
#pragma unroll
    for (int o = 16; o; o >>= 1) s += __shfl_xor_sync(0xffffffffu, s, o);
    float inv = 1.f / s;
#pragma unroll
    for (int i = 0; i < 32; i++) p[i] *= inv;

    float o0[32], o1[32];
#pragma unroll
    for (int i = 0; i < 32; i++) { o0[i] = 0.f; o1[i] = 0.f; }
#pragma unroll 1
    for (int j = 0; j < 16; j++) {
        __syncthreads();
#pragma unroll
        for (int it = 0; it < 4; it++)
            *(float4*)&Ts[(pr_r + it*16)*AT_TS + pr_c4] = pf[it];
        __syncthreads();
        if (j < 15) {
#pragma unroll
            for (int it = 0; it < 4; it++)
                pf[it] = *(const float4*)(v + bbase + (size_t)((j+1)*64 + pr_r + it*16) * DMODEL + pr_c4);
        }
#pragma unroll
        for (int ii = 0; ii < 2; ii++) {
            const int kr = l + 32*ii;
            const float pi = p[2*j + ii];
            const float4* trow = (const float4*)&Ts[kr*AT_TS];
#pragma unroll
            for (int d4 = 0; d4 < 8; d4++) {
                float4 tv = trow[d4];
                o0[d4*4+0] = fmaf(pi, tv.x, o0[d4*4+0]);
                o0[d4*4+1] = fmaf(pi, tv.y, o0[d4*4+1]);
                o0[d4*4+2] = fmaf(pi, tv.z, o0[d4*4+2]);
                o0[d4*4+3] = fmaf(pi, tv.w, o0[d4*4+3]);
            }
#pragma unroll
            for (int d4 = 0; d4 < 8; d4++) {
                float4 tv = trow[8 + d4];
                o1[d4*4+0] = fmaf(pi, tv.x, o1[d4*4+0]);
                o1[d4*4+1] = fmaf(pi, tv.y, o1[d4*4+1]);
                o1[d4*4+2] = fmaf(pi, tv.z, o1[d4*4+2]);
                o1[d4*4+3] = fmaf(pi, tv.w, o1[d4*4+3]);
            }
        }
    }
    float r0 = multi_reduce32(o0, l);
    float r1 = multi_reduce32(o1, l);
    size_t ob = bbase + (size_t)(qrow0 + w) * DMODEL;
    ao[ob + l] = r0;
    ao[ob + 32 + l] = r1;
}

extern "C" void kernel_launch(void* const* d_in, const int* in_sizes, int n_in,
                              void* d_out, int out_size)
{
    (void)in_sizes; (void)n_in; (void)out_size;
    const float* x   = (const float*)d_in[0];
    const float* n1w = (const float*)d_in[1];
    const float* Wq  = (const float*)d_in[2];  const float* bq = (const float*)d_in[3];
    const float* Wk  = (const float*)d_in[4];  const float* bk = (const float*)d_in[5];
    const float* Wv  = (const float*)d_in[6];  const float* bv = (const float*)d_in[7];
    const float* Wz  = (const float*)d_in[8];  const float* bz = (const float*)d_in[9];
    const float* Wg  = (const float*)d_in[10]; const float* bg = (const float*)d_in[11];
    const float* gdw = (const float*)d_in[12]; const float* gdb= (const float*)d_in[13];
    const float* guw = (const float*)d_in[14]; const float* gub= (const float*)d_in[15];
    const float* Wo  = (const float*)d_in[16]; const float* bo = (const float*)d_in[17];
    const float* n2w = (const float*)d_in[18];
    const float* f1w = (const float*)d_in[19]; const float* f1b= (const float*)d_in[20];
    const float* f2w = (const float*)d_in[21]; const float* f2b= (const float*)d_in[22];
    float* out = (float*)d_out;

    float *xn, *qp, *kp, *vp, *zp, *gmp, *t1, *hp, *attp, *aop, *yp, *ynp, *f1p;
    cudaGetSymbolAddress((void**)&xn,  g_xn);
    cudaGetSymbolAddress((void**)&qp,  g_q);
    cudaGetSymbolAddress((void**)&kp,  g_k);
    cudaGetSymbolAddress((void**)&vp,  g_v);
    cudaGetSymbolAddress((void**)&zp,  g_z);
    cudaGetSymbolAddress((void**)&gmp, g_gm);
    cudaGetSymbolAddress((void**)&t1,  g_t1);
    cudaGetSymbolAddress((void**)&hp,  g_h);
    cudaGetSymbolAddress((void**)&attp,g_att);
    cudaGetSymbolAddress((void**)&aop, g_ao);
    cudaGetSymbolAddress((void**)&yp,  g_y);
    cudaGetSymbolAddress((void**)&ynp, g_yn);
    cudaGetSymbolAddress((void**)&f1p, g_f1);

    cudaFuncSetAttribute(tgemm_kernel<0>, cudaFuncAttributeMaxDynamicSharedMemorySize, TG_SMEM_BYTES);
    cudaFuncSetAttribute(tgemm_kernel<1>, cudaFuncAttributeMaxDynamicSharedMemorySize, TG_SMEM_BYTES);
    cudaFuncSetAttribute(tgemm_kernel<2>, cudaFuncAttributeMaxDynamicSharedMemorySize, TG_SMEM_BYTES);
    cudaFuncSetAttribute(tgemm_kernel<3>, cudaFuncAttributeMaxDynamicSharedMemorySize, TG_SMEM_BYTES);
    cudaFuncSetAttribute(tgemm4_kernel,   cudaFuncAttributeMaxDynamicSharedMemorySize, TG_SMEM_BYTES);

    // 1. rmsnorm
    rmsnorm_kernel<<<NTOK, 256>>>(x, n1w, xn);
    // 2. Q/K/V/Z projections fused into one launch
    Quad quad;
    quad.p[0] = {Wq, bq, qp};
    quad.p[1] = {Wk, bk, kp};
    quad.p[2] = {Wv, bv, vp};
    quad.p[3] = {Wz, bz, zp};
    tgemm4_kernel<<<dim3(DMODEL/128, NTOK/128, 4), 256, TG_SMEM_BYTES>>>(xn, quad, DMODEL, DMODEL);
    // 3. gamma MLP
    tgemm_kernel<1><<<dim3(1, NTOK/128), 256, TG_SMEM_BYTES>>>(zp, gdw, gdb, nullptr, t1, NTOK, 128, DMODEL);
    tgemm_kernel<2><<<dim3(DMODEL/128, NTOK/128), 256, TG_SMEM_BYTES>>>(t1, guw, gub, nullptr, gmp, NTOK, DMODEL, 128);
    // 4. recurrence
    recurrence_kernel<<<REC_CTAS, 256>>>(zp, gmp, Wg, bg, hp);
    // 5. attention + Wo
    attn_kernel<<<4*16*128, 256>>>(qp, kp, vp, attp);
    tgemm_kernel<0><<<dim3(DMODEL/128, NTOK/128), 256, TG_SMEM_BYTES>>>(attp, Wo, bo, nullptr, aop, NTOK, DMODEL, DMODEL);
    // 6-7. residual + norm2, FFN, final residual (-> d_out)
    residual_norm_kernel<<<NTOK, 256>>>(x, aop, hp, n2w, yp, ynp);
    tgemm_kernel<3><<<dim3(FFDIM/128, NTOK/128), 256, TG_SMEM_BYTES>>>(ynp, f1w, f1b, nullptr, f1p, NTOK, FFDIM, DMODEL);
    tgemm_kernel<0><<<dim3(DMODEL/128, NTOK/128), 256, TG_SMEM_BYTES>>>(f1p, f2w, f2b, yp, out, NTOK, DMODEL, FFDIM);
}

// round 15
// speedup vs baseline: 1.1911x; 1.0875x over previous
#include <cuda_runtime.h>
#include <cstddef>
#include <cstdint>
#include <math.h>

#define DMODEL 1024
#define NTOK   4096
#define FFDIM  4096
#define SEQ    1024
#define REC_CTAS 128

__device__ float g_xn [NTOK*DMODEL];
__device__ float g_q  [NTOK*DMODEL];
__device__ float g_k  [NTOK*DMODEL];
__device__ float g_v  [NTOK*DMODEL];
__device__ float g_z  [NTOK*DMODEL];
__device__ float g_gm [NTOK*DMODEL];
__device__ float g_t1 [NTOK*128];
__device__ float g_h  [NTOK*DMODEL];
__device__ float g_att[NTOK*DMODEL];
__device__ float g_ao [NTOK*DMODEL];
__device__ float g_y  [NTOK*DMODEL];
__device__ float g_yn [NTOK*DMODEL];
__device__ float g_f1 [NTOK*FFDIM];
__device__ unsigned g_bar_count;
__device__ unsigned g_bar_sense;

// ---------------- helpers ----------------
__device__ __forceinline__ void mma_tf32(float* c,
    unsigned a0, unsigned a1, unsigned a2, unsigned a3,
    unsigned b0, unsigned b1)
{
    asm volatile("mma.sync.aligned.m16n8k8.row.col.f32.tf32.tf32.f32 "
                 "{%0,%1,%2,%3}, {%4,%5,%6,%7}, {%8,%9}, {%0,%1,%2,%3};\n"
                 : "+f"(c[0]), "+f"(c[1]), "+f"(c[2]), "+f"(c[3])
                 : "r"(a0), "r"(a1), "r"(a2), "r"(a3), "r"(b0), "r"(b1));
}

__device__ __forceinline__ void cp_async16(uint32_t dst_smem, const void* src) {
    asm volatile("cp.async.cg.shared.global [%0], [%1], 16;"
                 :: "r"(dst_smem), "l"(src));
}
__device__ __forceinline__ void cp_commit() {
    asm volatile("cp.async.commit_group;");
}

__device__ __forceinline__ float multi_reduce32(float (&acc)[32], int lane) {
#pragma unroll
    for (int d = 16; d >= 1; d >>= 1) {
        const bool up = (lane & d) != 0;
#pragma unroll
        for (int i = 0; i < d; i++) {
            float send = up ? acc[i] : acc[i + d];
            float recv = __shfl_xor_sync(0xffffffffu, send, d);
            float keep = up ? acc[i + d] : acc[i];
            acc[i] = keep + recv;
        }
    }
    return acc[0];
}

__device__ __forceinline__ float block_sum256(float v) {
    __shared__ float sred[9];
#pragma unroll
    for (int o = 16; o; o >>= 1) v += __shfl_xor_sync(0xffffffffu, v, o);
    int w = threadIdx.x >> 5, l = threadIdx.x & 31;
    if (l == 0) sred[w] = v;
    __syncthreads();
    if (threadIdx.x < 32) {
        float t = (l < 8) ? sred[l] : 0.f;
#pragma unroll
        for (int o = 4; o; o >>= 1) t += __shfl_xor_sync(0xffffffffu, t, o);
        if (l == 0) sred[8] = t;
    }
    __syncthreads();
    return sred[8];
}

__global__ __launch_bounds__(256)
void rmsnorm_kernel(const float* __restrict__ x, const float* __restrict__ w,
                    float* __restrict__ out) {
    const size_t base = (size_t)blockIdx.x * DMODEL;
    float vb[4]; float ss = 0.f;
#pragma unroll
    for (int i = 0; i < 4; i++) { float t = x[base + threadIdx.x + 256*i]; vb[i] = t; ss += t*t; }
    float inv = 1.f / (sqrtf(block_sum256(ss)) * 0.03125f + 1e-6f);
#pragma unroll
    for (int i = 0; i < 4; i++) { int c = threadIdx.x + 256*i; out[base + c] = w[c] * vb[i] * inv; }
}

__global__ __launch_bounds__(256)
void residual_norm_kernel(const float* __restrict__ x, const float* __restrict__ ao,
                          const float* __restrict__ hs, const float* __restrict__ w,
                          float* __restrict__ y, float* __restrict__ yn) {
    const size_t base = (size_t)blockIdx.x * DMODEL;
    float vb[4]; float ss = 0.f;
#pragma unroll
    for (int i = 0; i < 4; i++) {
        int c = threadIdx.x + 256*i;
        float t = x[base+c] + ao[base+c] + hs[base+c];
        vb[i] = t; y[base+c] = t; ss += t*t;
    }
    float inv = 1.f / (sqrtf(block_sum256(ss)) * 0.03125f + 1e-6f);
#pragma unroll
    for (int i = 0; i < 4; i++) { int c = threadIdx.x + 256*i; yn[base+c] = w[c] * vb[i] * inv; }
}

// ---------------- TF32 tensor-core GEMM (R10 exact: 3-stage cp.async ring) ----
#define TG_BK 16
#define TG_RS 20
#define TG_STAGE (128*TG_RS)
#define TG_SMEM_BYTES (2*3*TG_STAGE*4)

template<int EPI>
__device__ __forceinline__
void tgemm_body(const float* __restrict__ A, const float* __restrict__ B,
                const float* __restrict__ bias, const float* __restrict__ res,
                float* __restrict__ C, int N, int K,
                float* As, float* Bs, int bm, int bn)
{
    const int tid = threadIdx.x;
    const int wid = tid >> 5, lane = tid & 31;
    const int gq = lane >> 2, tq = lane & 3;
    const int m0 = (wid & 1) * 64, n0 = (wid >> 1) * 32;

    const int crow = tid >> 1;
    const int ck  = (tid & 1) * 8;
    const float* Ap = A + (size_t)(bm + crow) * K + ck;
    const float* Bp = B + (size_t)(bn + crow) * K + ck;

    uint32_t aSt[3], bSt[3];
#pragma unroll
    for (int st = 0; st < 3; st++) {
        aSt[st] = (uint32_t)__cvta_generic_to_shared(&As[st*TG_STAGE + crow*TG_RS + ck]);
        bSt[st] = (uint32_t)__cvta_generic_to_shared(&Bs[st*TG_STAGE + crow*TG_RS + ck]);
    }

    float acc[4][4][4];
#pragma unroll
    for (int i = 0; i < 4; i++)
#pragma unroll
        for (int j = 0; j < 4; j++)
#pragma unroll
            for (int e = 0; e < 4; e++) acc[i][j][e] = 0.f;

    cp_async16(aSt[0],      Ap);     cp_async16(aSt[0] + 16, Ap + 4);
    cp_async16(bSt[0],      Bp);     cp_async16(bSt[0] + 16, Bp + 4);
    cp_commit();
    if (TG_BK < K) {
        cp_async16(aSt[1],      Ap + TG_BK);     cp_async16(aSt[1] + 16, Ap + TG_BK + 4);
        cp_async16(bSt[1],      Bp + TG_BK);     cp_async16(bSt[1] + 16, Bp + TG_BK + 4);
    }
    cp_commit();

    int s = 0, s2 = 2;
    for (int kt = 0; kt < K; kt += TG_BK) {
        asm volatile("cp.async.wait_group 1;");
        __syncthreads();
        if (kt + 2*TG_BK < K) {
            const float* An = Ap + kt + 2*TG_BK;
            const float* Bn = Bp + kt + 2*TG_BK;
            cp_async16(aSt[s2],      An);     cp_async16(aSt[s2] + 16, An + 4);
            cp_async16(bSt[s2],      Bn);     cp_async16(bSt[s2] + 16, Bn + 4);
        }
        cp_commit();

        const float* Asb = As + s*TG_STAGE;
        const float* Bsb = Bs + s*TG_STAGE;
#pragma unroll
        for (int kb = 0; kb < TG_BK; kb += 8) {
            unsigned bf[4][2];
#pragma unroll
            for (int j = 0; j < 4; j++) {
                const int n = n0 + j*8 + gq;
                bf[j][0] = __float_as_uint(Bsb[n*TG_RS + kb+tq]);
                bf[j][1] = __float_as_uint(Bsb[n*TG_RS + kb+tq+4]);
            }
#pragma unroll
            for (int i = 0; i < 4; i++) {
                const int r = m0 + i*16 + gq;
                unsigned a0 = __float_as_uint(Asb[(r  )*TG_RS + kb+tq]);
                unsigned a1 = __float_as_uint(Asb[(r+8)*TG_RS + kb+tq]);
                unsigned a2 = __float_as_uint(Asb[(r  )*TG_RS + kb+tq+4]);
                unsigned a3 = __float_as_uint(Asb[(r+8)*TG_RS + kb+tq+4]);
#pragma unroll
                for (int j = 0; j < 4; j++)
                    mma_tf32(acc[i][j], a0, a1, a2, a3, bf[j][0], bf[j][1]);
            }
        }
        s  = (s  == 2) ? 0 : s  + 1;
        s2 = (s2 == 2) ? 0 : s2 + 1;
    }

#pragma unroll
    for (int i = 0; i < 4; i++) {
#pragma unroll
        for (int half = 0; half < 2; half++) {
            const int gr = bm + m0 + i*16 + gq + half*8;
            float* crowp = C + (size_t)gr * N;
            const float* rrow = res ? res + (size_t)gr * N : nullptr;
#pragma unroll
            for (int j = 0; j < 4; j++) {
                const int gc = bn + n0 + j*8 + tq*2;
#pragma unroll
                for (int e = 0; e < 2; e++) {
                    float vv = acc[i][j][half*2 + e] + bias[gc + e];
                    if (EPI == 1) vv = fmaxf(vv, 0.f);
                    else if (EPI == 2) {
                        vv = 1.f / (1.f + __expf(-vv));
                        vv = fminf(fmaxf(vv, 1e-6f), 1.f - 1e-6f);
                    } else if (EPI == 3) {
                        float u = 0.7978845608028654f * (vv + 0.044715f * vv * vv * vv);
                        vv = 0.5f * vv * (1.f + tanhf(u));
                    }
                    if (rrow) vv += rrow[gc + e];
                    crowp[gc + e] = vv;
                }
            }
        }
    }
}

template<int EPI>
__global__ __launch_bounds__(256, 2)
void tgemm_kernel(const float* __restrict__ A, const float* __restrict__ B,
                  const float* __restrict__ bias, const float* __restrict__ res,
                  float* __restrict__ C, int M, int N, int K)
{
    extern __shared__ float dsm[];
    tgemm_body<EPI>(A, B, bias, res, C, N, K, dsm, dsm + 3*TG_STAGE,
                    blockIdx.y * 128, blockIdx.x * 128);
}

struct Ptr3 { const float* B; const float* bias; float* C; };
struct Quad { Ptr3 p[4]; };

__global__ __launch_bounds__(256, 2)
void tgemm4_kernel(const float* __restrict__ A, Quad q, int N, int K)
{
    extern __shared__ float dsm[];
    Ptr3 pr = q.p[blockIdx.z];
    tgemm_body<0>(A, pr.B, pr.bias, nullptr, pr.C, N, K, dsm, dsm + 3*TG_STAGE,
                  blockIdx.y * 128, blockIdx.x * 128);
}

// ================= merged recurrence + attention =================
// blockIdx.x < 128  -> recurrence CTA (persistent, grid barrier over 128)
// blockIdx.x >= 128 -> attention CTA (8192 of them)
// B300 wave-1 placement is deterministic, so blocks 0..127 are co-resident.
#define AT_TS 68

__device__ void recurrence_body(
    const float* __restrict__ z, const float* __restrict__ gm,
    const float* __restrict__ Wg, const float* __restrict__ bg,
    float* __restrict__ hs, float* red)
{
    const int tid = threadIdx.x, w = tid >> 5, l = tid & 31;
    const int blk = blockIdx.x;
    const int k0 = w * 128 + l * 4;
    float4 wv[8];
#pragma unroll
    for (int r = 0; r < 8; r++)
        wv[r] = *(const float4*)(Wg + (size_t)(blk*8 + r) * DMODEL + k0);

    float bgv = 0.f, hprev = 0.f; int jout = 0, bout = 0;
    if (tid < 32) { jout = blk*8 + (tid >> 2); bout = tid & 3; bgv = bg[jout]; }

    for (int t = 0; t < SEQ; t++) {
        float acc[32];
#pragma unroll
        for (int a = 0; a < 32; a++) acc[a] = 0.f;
        if (t > 0) {
#pragma unroll
            for (int b = 0; b < 4; b++) {
                float4 hv = __ldcg((const float4*)(hs + ((size_t)b*SEQ + (t-1))*DMODEL + k0));
#pragma unroll
                for (int r = 0; r < 8; r++) {
                    acc[r*4+b] = fmaf(wv[r].x, hv.x, acc[r*4+b]);
                    acc[r*4+b] = fmaf(wv[r].y, hv.y, acc[r*4+b]);
                    acc[r*4+b] = fmaf(wv[r].z, hv.z, acc[r*4+b]);
                    acc[r*4+b] = fmaf(wv[r].w, hv.w, acc[r*4+b]);
                }
            }
        }
        float part = multi_reduce32(acc, l);
        red[w*32 + l] = part;
        __syncthreads();
        if (tid < 32) {
            float sum = bgv;
#pragma unroll
            for (int ww = 0; ww < 8; ww++) sum += red[ww*32 + tid];
            float sig = 1.f / (1.f + __expf(-sum));
            size_t base = ((size_t)bout * SEQ + t) * DMODEL + jout;
            hprev = z[base] * sig + gm[base] * hprev;
            hs[base] = hprev;
            __threadfence();
        }
        __syncthreads();
        if (tid == 0) {
            unsigned sv = *(volatile unsigned*)&g_bar_sense;
            unsigned prev = atomicAdd(&g_bar_count, 1u);
            if (prev == REC_CTAS - 1) {
                g_bar_count = 0;
                __threadfence();
                atomicExch(&g_bar_sense, sv ^ 1u);
            } else {
                while (*(volatile unsigned*)&g_bar_sense == sv) { }
            }
            __threadfence();
        }
        __syncthreads();
    }
}

__device__ void attn_body(
    const float* __restrict__ q, const float* __restrict__ k,
    const float* __restrict__ v, float* __restrict__ ao,
    int abid, float (*Qs)[64], float* Ts)
{
    const int qb = abid & 127;
    const int bh = abid >> 7;
    const int b = bh >> 4, h = bh & 15;
    const int tid = threadIdx.x, w = tid >> 5, l = tid & 31;
    const size_t bbase = (size_t)b * SEQ * DMODEL + (size_t)h * 64;
    const int qrow0 = qb * 8;

    const int pr_r  = tid >> 4;
    const int pr_c4 = (tid & 15) * 4;

    if (tid < 128) {
        int r = tid >> 4, c4 = (tid & 15) * 4;
        float4 t = *(const float4*)(q + bbase + (size_t)(qrow0 + r) * DMODEL + c4);
        *(float4*)&Qs[r][c4] = t;
    }

    float4 pf[4];
#pragma unroll
    for (int it = 0; it < 4; it++)
        pf[it] = *(const float4*)(k + bbase + (size_t)(pr_r + it*16) * DMODEL + pr_c4);

    __syncthreads();
    float4 qreg[16];
#pragma unroll
    for (int i = 0; i < 16; i++) qreg[i] = *(const float4*)&Qs[w][i*4];

    float p[32];
#pragma unroll 1
    for (int j = 0; j < 16; j++) {
        __syncthreads();
#pragma unroll
        for (int it = 0; it < 4; it++)
            *(float4*)&Ts[(pr_r + it*16)*AT_TS + pr_c4] = pf[it];
        __syncthreads();
        if (j < 15) {
#pragma unroll
            for (int it = 0; it < 4; it++)
                pf[it] = *(const float4*)(k + bbase + (size_t)((j+1)*64 + pr_r + it*16) * DMODEL + pr_c4);
        }
#pragma unroll
        for (int ii = 0; ii < 2; ii++) {
            const int kr = l + 32*ii;
            const float4* trow = (const float4*)&Ts[kr*AT_TS];
            float s = 0.f;
#pragma unroll
            for (int i = 0; i < 16; i++) {
                float4 tv = trow[i];
                s = fmaf(qreg[i].x, tv.x, s);
                s = fmaf(qreg[i].y, tv.y, s);
                s = fmaf(qreg[i].z, tv.z, s);
                s = fmaf(qreg[i].w, tv.w, s);
            }
            p[2*j + ii] = s * 0.125f;
        }
    }

#pragma unroll
    for (int it = 0; it < 4; it++)
        pf[it] = *(const float4*)(v + bbase + (size_t)(pr_r + it*16) * DMODEL + pr_c4);

    float m = -3.0e38f;
#pragma unroll
    for (int i = 0; i < 32; i++) m = fmaxf(m, p[i]);
#pragma unroll
    for (int o = 16; o; o >>= 1) m = fmaxf(m, __shfl_xor_sync(0xffffffffu, m, o));
    float s = 0.f;
#pragma unroll
    for (int i = 0; i < 32; i++) { p[i] = __expf(p[i] - m); s += p[i]; }
#pragma unroll
    for (int o = 16; o; o >>= 1) s += __shfl_xor_sync(0xffffffffu, s, o);
    float inv = 1.f / s;
#pragma unroll
    for (int i = 0; i < 32; i++) p[i] *= inv;

    float o0[32], o1[32];
#pragma unroll
    for (int i = 0; i < 32; i++) { o0[i] = 0.f; o1[i] = 0.f; }
#pragma unroll 1
    for (int j = 0; j < 16; j++) {
        __syncthreads();
#pragma unroll
        for (int it = 0; it < 4; it++)
            *(float4*)&Ts[(pr_r + it*16)*AT_TS + pr_c4] = pf[it];
        __syncthreads();
        if (j < 15) {
#pragma unroll
            for (int it = 0; it < 4; it++)
                pf[it] = *(const float4*)(v + bbase + (size_t)((j+1)*64 + pr_r + it*16) * DMODEL + pr_c4);
        }
#pragma unroll
        for (int ii = 0; ii < 2; ii++) {
            const int kr = l + 32*ii;
            const float pi = p[2*j + ii];
            const float4* trow = (const float4*)&Ts[kr*AT_TS];
#pragma unroll
            for (int d4 = 0; d4 < 8; d4++) {
                float4 tv = trow[d4];
                o0[d4*4+0] = fmaf(pi, tv.x, o0[d4*4+0]);
                o0[d4*4+1] = fmaf(pi, tv.y, o0[d4*4+1]);
                o0[d4*4+2] = fmaf(pi, tv.z, o0[d4*4+2]);
                o0[d4*4+3] = fmaf(pi, tv.w, o0[d4*4+3]);
            }
#pragma unroll
            for (int d4 = 0; d4 < 8; d4++) {
                float4 tv = trow[8 + d4];
                o1[d4*4+0] = fmaf(pi, tv.x, o1[d4*4+0]);
                o1[d4*4+1] = fmaf(pi, tv.y, o1[d4*4+1]);
                o1[d4*4+2] = fmaf(pi, tv.z, o1[d4*4+2]);
                o1[d4*4+3] = fmaf(pi, tv.w, o1[d4*4+3]);
            }
        }
    }
    float r0 = multi_reduce32(o0, l);
    float r1 = multi_reduce32(o1, l);
    size_t ob = bbase + (size_t)(qrow0 + w) * DMODEL;
    ao[ob + l] = r0;
    ao[ob + 32 + l] = r1;
}

__global__ __launch_bounds__(256)
void rec_attn_kernel(
    const float* __restrict__ z, const float* __restrict__ gm,
    const float* __restrict__ Wg, const float* __restrict__ bg,
    float* __restrict__ hs,
    const float* __restrict__ q, const float* __restrict__ k,
    const float* __restrict__ v, float* __restrict__ ao)
{
    __shared__ float red[256];
    __shared__ float Qs[8][64];
    __shared__ float Ts[64*AT_TS];
    if (blockIdx.x < REC_CTAS) {
        recurrence_body(z, gm, Wg, bg, hs, red);
    } else {
        attn_body(q, k, v, ao, blockIdx.x - REC_CTAS, Qs, Ts);
    }
}

extern "C" void kernel_launch(void* const* d_in, const int* in_sizes, int n_in,
                              void* d_out, int out_size)
{
    (void)in_sizes; (void)n_in; (void)out_size;
    const float* x   = (const float*)d_in[0];
    const float* n1w = (const float*)d_in[1];
    const float* Wq  = (const float*)d_in[2];  const float* bq = (const float*)d_in[3];
    const float* Wk  = (const float*)d_in[4];  const float* bk = (const float*)d_in[5];
    const float* Wv  = (const float*)d_in[6];  const float* bv = (const float*)d_in[7];
    const float* Wz  = (const float*)d_in[8];  const float* bz = (const float*)d_in[9];
    const float* Wg  = (const float*)d_in[10]; const float* bg = (const float*)d_in[11];
    const float* gdw = (const float*)d_in[12]; const float* gdb= (const float*)d_in[13];
    const float* guw = (const float*)d_in[14]; const float* gub= (const float*)d_in[15];
    const float* Wo  = (const float*)d_in[16]; const float* bo = (const float*)d_in[17];
    const float* n2w = (const float*)d_in[18];
    const float* f1w = (const float*)d_in[19]; const float* f1b= (const float*)d_in[20];
    const float* f2w = (const float*)d_in[21]; const float* f2b= (const float*)d_in[22];
    float* out = (float*)d_out;

    float *xn, *qp, *kp, *vp, *zp, *gmp, *t1, *hp, *attp, *aop, *yp, *ynp, *f1p;
    cudaGetSymbolAddress((void**)&xn,  g_xn);
    cudaGetSymbolAddress((void**)&qp,  g_q);
    cudaGetSymbolAddress((void**)&kp,  g_k);
    cudaGetSymbolAddress((void**)&vp,  g_v);
    cudaGetSymbolAddress((void**)&zp,  g_z);
    cudaGetSymbolAddress((void**)&gmp, g_gm);
    cudaGetSymbolAddress((void**)&t1,  g_t1);
    cudaGetSymbolAddress((void**)&hp,  g_h);
    cudaGetSymbolAddress((void**)&attp,g_att);
    cudaGetSymbolAddress((void**)&aop, g_ao);
    cudaGetSymbolAddress((void**)&yp,  g_y);
    cudaGetSymbolAddress((void**)&ynp, g_yn);
    cudaGetSymbolAddress((void**)&f1p, g_f1);

    cudaFuncSetAttribute(tgemm_kernel<0>, cudaFuncAttributeMaxDynamicSharedMemorySize, TG_SMEM_BYTES);
    cudaFuncSetAttribute(tgemm_kernel<1>, cudaFuncAttributeMaxDynamicSharedMemorySize, TG_SMEM_BYTES);
    cudaFuncSetAttribute(tgemm_kernel<2>, cudaFuncAttributeMaxDynamicSharedMemorySize, TG_SMEM_BYTES);
    cudaFuncSetAttribute(tgemm_kernel<3>, cudaFuncAttributeMaxDynamicSharedMemorySize, TG_SMEM_BYTES);
    cudaFuncSetAttribute(tgemm4_kernel,   cudaFuncAttributeMaxDynamicSharedMemorySize, TG_SMEM_BYTES);

    // 1. rmsnorm
    rmsnorm_kernel<<<NTOK, 256>>>(x, n1w, xn);
    // 2. Q/K/V/Z projections fused into one launch
    Quad quad;
    quad.p[0] = {Wq, bq, qp};
    quad.p[1] = {Wk, bk, kp};
    quad.p[2] = {Wv, bv, vp};
    quad.p[3] = {Wz, bz, zp};
    tgemm4_kernel<<<dim3(DMODEL/128, NTOK/128, 4), 256, TG_SMEM_BYTES>>>(xn, quad, DMODEL, DMODEL);
    // 3. gamma MLP
    tgemm_kernel<1><<<dim3(1, NTOK/128), 256, TG_SMEM_BYTES>>>(zp, gdw, gdb, nullptr, t1, NTOK, 128, DMODEL);
    tgemm_kernel<2><<<dim3(DMODEL/128, NTOK/128), 256, TG_SMEM_BYTES>>>(t1, guw, gub, nullptr, gmp, NTOK, DMODEL, 128);
    // 4+5a. recurrence (blocks 0..127, persistent) + attention (blocks 128..8319), overlapped
    rec_attn_kernel<<<REC_CTAS + 4*16*128, 256>>>(zp, gmp, Wg, bg, hp, qp, kp, vp, attp);
    // 5b. Wo projection
    tgemm_kernel<0><<<dim3(DMODEL/128, NTOK/128), 256, TG_SMEM_BYTES>>>(attp, Wo, bo, nullptr, aop, NTOK, DMODEL, DMODEL);
    // 6-7. residual + norm2, FFN, final residual (-> d_out)
    residual_norm_kernel<<<NTOK, 256>>>(x, aop, hp, n2w, yp, ynp);
    tgemm_kernel<3><<<dim3(FFDIM/128, NTOK/128), 256, TG_SMEM_BYTES>>>(ynp, f1w, f1b, nullptr, f1p, NTOK, FFDIM, DMODEL);
    tgemm_kernel<0><<<dim3(DMODEL/128, NTOK/128), 256, TG_SMEM_BYTES>>>(f1p, f2w, f2b, yp, out, NTOK, DMODEL, FFDIM);
}

// round 16
// speedup vs baseline: 1.3049x; 1.0955x over previous
#include <cuda_runtime.h>
#include <cuda_fp16.h>
#include <cstddef>
#include <cstdint>
#include <math.h>

#define DMODEL 1024
#define NTOK   4096
#define FFDIM  4096
#define SEQ    1024
#define REC_CTAS 128

// f32 scratch
__device__ float g_q  [NTOK*DMODEL];
__device__ float g_k  [NTOK*DMODEL];
__device__ float g_v  [NTOK*DMODEL];
__device__ float g_z  [NTOK*DMODEL];
__device__ float g_gm [NTOK*DMODEL];
__device__ float g_h  [NTOK*DMODEL];
__device__ float g_ao [NTOK*DMODEL];
__device__ float g_y  [NTOK*DMODEL];
__device__ unsigned g_bar_count;
__device__ unsigned g_bar_sense;

// fp16 scratch (activations + converted weights)
__device__ __align__(16) __half g_xn_h [NTOK*DMODEL];
__device__ __align__(16) __half g_z_h  [NTOK*DMODEL];
__device__ __align__(16) __half g_t1_h [NTOK*128];
__device__ __align__(16) __half g_att_h[NTOK*DMODEL];
__device__ __align__(16) __half g_yn_h [NTOK*DMODEL];
__device__ __align__(16) __half g_f1_h [NTOK*FFDIM];
__device__ __align__(16) __half g_wq_h [DMODEL*DMODEL];
__device__ __align__(16) __half g_wk_h [DMODEL*DMODEL];
__device__ __align__(16) __half g_wv_h [DMODEL*DMODEL];
__device__ __align__(16) __half g_wz_h [DMODEL*DMODEL];
__device__ __align__(16) __half g_wo_h [DMODEL*DMODEL];
__device__ __align__(16) __half g_f1w_h[FFDIM*DMODEL];
__device__ __align__(16) __half g_f2w_h[DMODEL*FFDIM];
__device__ __align__(16) __half g_gdw_h[128*DMODEL];
__device__ __align__(16) __half g_guw_h[DMODEL*128];

// ---------------- helpers ----------------
__device__ __forceinline__ void mma_f16(float* c,
    unsigned a0, unsigned a1, unsigned a2, unsigned a3,
    unsigned b0, unsigned b1)
{
    asm volatile("mma.sync.aligned.m16n8k16.row.col.f32.f16.f16.f32 "
                 "{%0,%1,%2,%3}, {%4,%5,%6,%7}, {%8,%9}, {%0,%1,%2,%3};\n"
                 : "+f"(c[0]), "+f"(c[1]), "+f"(c[2]), "+f"(c[3])
                 : "r"(a0), "r"(a1), "r"(a2), "r"(a3), "r"(b0), "r"(b1));
}

__device__ __forceinline__ void cp_async16(uint32_t dst_smem, const void* src) {
    asm volatile("cp.async.cg.shared.global [%0], [%1], 16;"
                 :: "r"(dst_smem), "l"(src));
}
__device__ __forceinline__ void cp_commit() {
    asm volatile("cp.async.commit_group;");
}

__device__ __forceinline__ float multi_reduce32(float (&acc)[32], int lane) {
#pragma unroll
    for (int d = 16; d >= 1; d >>= 1) {
        const bool up = (lane & d) != 0;
#pragma unroll
        for (int i = 0; i < d; i++) {
            float send = up ? acc[i] : acc[i + d];
            float recv = __shfl_xor_sync(0xffffffffu, send, d);
            float keep = up ? acc[i + d] : acc[i];
            acc[i] = keep + recv;
        }
    }
    return acc[0];
}

__device__ __forceinline__ float block_sum256(float v) {
    __shared__ float sred[9];
#pragma unroll
    for (int o = 16; o; o >>= 1) v += __shfl_xor_sync(0xffffffffu, v, o);
    int w = threadIdx.x >> 5, l = threadIdx.x & 31;
    if (l == 0) sred[w] = v;
    __syncthreads();
    if (threadIdx.x < 32) {
        float t = (l < 8) ? sred[l] : 0.f;
#pragma unroll
        for (int o = 4; o; o >>= 1) t += __shfl_xor_sync(0xffffffffu, t, o);
        if (l == 0) sred[8] = t;
    }
    __syncthreads();
    return sred[8];
}

// weight f32 -> f16 conversion (runs every launch; deterministic)
struct CJob { const float* s; __half* d; int n; };
struct CJobs { CJob j[9]; };
__global__ __launch_bounds__(256)
void cvt_kernel(CJobs jobs) {
    CJob job = jobs.j[blockIdx.y];
    const int nh = job.n >> 1;
    const int stride = gridDim.x * blockDim.x;
    for (int i = blockIdx.x * blockDim.x + threadIdx.x; i < nh; i += stride) {
        float2 f = ((const float2*)job.s)[i];
        ((__half2*)job.d)[i] = __floats2half2_rn(f.x, f.y);
    }
}

__global__ __launch_bounds__(256)
void rmsnorm_kernel(const float* __restrict__ x, const float* __restrict__ w,
                    __half* __restrict__ outh) {
    const size_t base = (size_t)blockIdx.x * DMODEL;
    float vb[4]; float ss = 0.f;
#pragma unroll
    for (int i = 0; i < 4; i++) { float t = x[base + threadIdx.x + 256*i]; vb[i] = t; ss += t*t; }
    float inv = 1.f / (sqrtf(block_sum256(ss)) * 0.03125f + 1e-6f);
#pragma unroll
    for (int i = 0; i < 4; i++) {
        int c = threadIdx.x + 256*i;
        outh[base + c] = __float2half_rn(w[c] * vb[i] * inv);
    }
}

__global__ __launch_bounds__(256)
void residual_norm_kernel(const float* __restrict__ x, const float* __restrict__ ao,
                          const float* __restrict__ hs, const float* __restrict__ w,
                          float* __restrict__ y, __half* __restrict__ ynh) {
    const size_t base = (size_t)blockIdx.x * DMODEL;
    float vb[4]; float ss = 0.f;
#pragma unroll
    for (int i = 0; i < 4; i++) {
        int c = threadIdx.x + 256*i;
        float t = x[base+c] + ao[base+c] + hs[base+c];
        vb[i] = t; y[base+c] = t; ss += t*t;
    }
    float inv = 1.f / (sqrtf(block_sum256(ss)) * 0.03125f + 1e-6f);
#pragma unroll
    for (int i = 0; i < 4; i++) {
        int c = threadIdx.x + 256*i;
        ynh[base + c] = __float2half_rn(w[c] * vb[i] * inv);
    }
}

// ---------------- FP16 tensor-core GEMM (m16n8k16, 3-stage cp.async ring) -----
// C[M,N] = A[M,K] @ B[N,K]^T + bias. A,B fp16; accum f32. Block 128x128, BK=32.
// SMEM: 64B rows, chunk swizzle c^((r>>1)&3) -> conflict-free LDS.32 frags.
#define HG_BK    32
#define HG_STAGE 8192
#define HG_SMEM_BYTES (6*HG_STAGE)

template<int EPI>
__device__ __forceinline__
void hgemm_body(const __half* __restrict__ A, const __half* __restrict__ B,
                const float* __restrict__ bias, const float* __restrict__ res,
                float* __restrict__ Cf, __half* __restrict__ Ch,
                int N, int K, char* hsm, int bm, int bn)
{
    const int tid = threadIdx.x;
    const int wid = tid >> 5, lane = tid & 31;
    const int gq = lane >> 2, tq = lane & 3;
    const int m0 = (wid & 1) * 64, n0 = (wid >> 1) * 32;

    const int frow = tid >> 1;                 // fill row
    const int fc0  = (tid & 1) * 2;            // first logical 16B chunk (of 4)
    const int fsw  = (frow >> 1) & 3;
    const __half* Ap = A + (size_t)(bm + frow) * K + fc0 * 8;
    const __half* Bp = B + (size_t)(bn + frow) * K + fc0 * 8;

    const uint32_t base = (uint32_t)__cvta_generic_to_shared(hsm);
    uint32_t dA[3][2], dB[3][2];
#pragma unroll
    for (int st = 0; st < 3; st++) {
#pragma unroll
        for (int c = 0; c < 2; c++) {
            uint32_t off = frow * 64u + (uint32_t)(((fc0 + c) ^ fsw) << 4);
            dA[st][c] = base + st * HG_STAGE + off;
            dB[st][c] = base + 3 * HG_STAGE + st * HG_STAGE + off;
        }
    }

    float acc[4][4][4];
#pragma unroll
    for (int i = 0; i < 4; i++)
#pragma unroll
        for (int j = 0; j < 4; j++)
#pragma unroll
            for (int e = 0; e < 4; e++) acc[i][j][e] = 0.f;

    const int NC = K / HG_BK;
    // prologue: chunks (in halves) per tile = 32; thread's two chunks at +0,+8
    cp_async16(dA[0][0], Ap);      cp_async16(dA[0][1], Ap + 8);
    cp_async16(dB[0][0], Bp);      cp_async16(dB[0][1], Bp + 8);
    cp_commit();
    if (NC > 1) {
        cp_async16(dA[1][0], Ap + HG_BK);      cp_async16(dA[1][1], Ap + HG_BK + 8);
        cp_async16(dB[1][0], Bp + HG_BK);      cp_async16(dB[1][1], Bp + HG_BK + 8);
    }
    cp_commit();

    int s = 0, s2 = 2;
    for (int t = 0; t < NC; t++) {
        asm volatile("cp.async.wait_group 1;");
        __syncthreads();
        if (t + 2 < NC) {
            const __half* An = Ap + (size_t)(t + 2) * HG_BK;
            const __half* Bn = Bp + (size_t)(t + 2) * HG_BK;
            cp_async16(dA[s2][0], An);      cp_async16(dA[s2][1], An + 8);
            cp_async16(dB[s2][0], Bn);      cp_async16(dB[s2][1], Bn + 8);
        }
        cp_commit();

        const char* Ab = hsm + s * HG_STAGE;
        const char* Bb = hsm + 3 * HG_STAGE + s * HG_STAGE;
#pragma unroll
        for (int ks = 0; ks < 2; ks++) {
            unsigned bf[4][2];
#pragma unroll
            for (int j = 0; j < 4; j++) {
                const int n = n0 + j*8 + gq;
                const int sw = (n >> 1) & 3;
                bf[j][0] = *(const uint32_t*)(Bb + n*64 + (((2*ks  ) ^ sw) << 4) + 4*tq);
                bf[j][1] = *(const uint32_t*)(Bb + n*64 + (((2*ks+1) ^ sw) << 4) + 4*tq);
            }
#pragma unroll
            for (int i = 0; i < 4; i++) {
                const int r = m0 + i*16 + gq;
                const int sw = (r >> 1) & 3;   // same for r and r+8
                const int c0off = (((2*ks  ) ^ sw) << 4) + 4*tq;
                const int c1off = (((2*ks+1) ^ sw) << 4) + 4*tq;
                unsigned a0 = *(const uint32_t*)(Ab + r*64 + c0off);
                unsigned a1 = *(const uint32_t*)(Ab + (r+8)*64 + c0off);
                unsigned a2 = *(const uint32_t*)(Ab + r*64 + c1off);
                unsigned a3 = *(const uint32_t*)(Ab + (r+8)*64 + c1off);
#pragma unroll
                for (int j = 0; j < 4; j++)
                    mma_f16(acc[i][j], a0, a1, a2, a3, bf[j][0], bf[j][1]);
            }
        }
        s  = (s  == 2) ? 0 : s  + 1;
        s2 = (s2 == 2) ? 0 : s2 + 1;
    }

#pragma unroll
    for (int i = 0; i < 4; i++) {
#pragma unroll
        for (int half = 0; half < 2; half++) {
            const int gr = bm + m0 + i*16 + gq + half*8;
            float* cfr = Cf ? Cf + (size_t)gr * N : nullptr;
            __half* chr = Ch ? Ch + (size_t)gr * N : nullptr;
            const float* rrow = res ? res + (size_t)gr * N : nullptr;
#pragma unroll
            for (int j = 0; j < 4; j++) {
                const int gc = bn + n0 + j*8 + tq*2;
                float vv2[2];
#pragma unroll
                for (int e = 0; e < 2; e++) {
                    float vv = acc[i][j][half*2 + e] + bias[gc + e];
                    if (EPI == 1) vv = fmaxf(vv, 0.f);
                    else if (EPI == 2) {
                        vv = 1.f / (1.f + __expf(-vv));
                        vv = fminf(fmaxf(vv, 1e-6f), 1.f - 1e-6f);
                    } else if (EPI == 3) {
                        float u = 0.7978845608028654f * (vv + 0.044715f * vv * vv * vv);
                        vv = 0.5f * vv * (1.f + tanhf(u));
                    }
                    if (rrow) vv += rrow[gc + e];
                    vv2[e] = vv;
                }
                if (cfr) { cfr[gc] = vv2[0]; cfr[gc + 1] = vv2[1]; }
                if (chr) *(__half2*)(chr + gc) = __floats2half2_rn(vv2[0], vv2[1]);
            }
        }
    }
}

template<int EPI>
__global__ __launch_bounds__(256, 2)
void hgemm_kernel(const __half* __restrict__ A, const __half* __restrict__ B,
                  const float* __restrict__ bias, const float* __restrict__ res,
                  float* __restrict__ Cf, __half* __restrict__ Ch, int N, int K)
{
    extern __shared__ char hsm[];
    hgemm_body<EPI>(A, B, bias, res, Cf, Ch, N, K, hsm,
                    blockIdx.y * 128, blockIdx.x * 128);
}

struct HPtr { const __half* B; const float* bias; float* Cf; __half* Ch; };
struct HQuad { HPtr p[4]; };

__global__ __launch_bounds__(256, 2)
void hgemm4_kernel(const __half* __restrict__ A, HQuad q, int N, int K)
{
    extern __shared__ char hsm[];
    HPtr pr = q.p[blockIdx.z];
    hgemm_body<0>(A, pr.B, pr.bias, nullptr, pr.Cf, pr.Ch, N, K, hsm,
                  blockIdx.y * 128, blockIdx.x * 128);
}

// ================= merged recurrence + attention (R14 winner) =================
#define AT_TS 68

__device__ void recurrence_body(
    const float* __restrict__ z, const float* __restrict__ gm,
    const float* __restrict__ Wg, const float* __restrict__ bg,
    float* __restrict__ hs, float* red)
{
    const int tid = threadIdx.x, w = tid >> 5, l = tid & 31;
    const int blk = blockIdx.x;
    const int k0 = w * 128 + l * 4;
    float4 wv[8];
#pragma unroll
    for (int r = 0; r < 8; r++)
        wv[r] = *(const float4*)(Wg + (size_t)(blk*8 + r) * DMODEL + k0);

    float bgv = 0.f, hprev = 0.f; int jout = 0, bout = 0;
    if (tid < 32) { jout = blk*8 + (tid >> 2); bout = tid & 3; bgv = bg[jout]; }

    for (int t = 0; t < SEQ; t++) {
        float acc[32];
#pragma unroll
        for (int a = 0; a < 32; a++) acc[a] = 0.f;
        if (t > 0) {
#pragma unroll
            for (int b = 0; b < 4; b++) {
                float4 hv = __ldcg((const float4*)(hs + ((size_t)b*SEQ + (t-1))*DMODEL + k0));
#pragma unroll
                for (int r = 0; r < 8; r++) {
                    acc[r*4+b] = fmaf(wv[r].x, hv.x, acc[r*4+b]);
                    acc[r*4+b] = fmaf(wv[r].y, hv.y, acc[r*4+b]);
                    acc[r*4+b] = fmaf(wv[r].z, hv.z, acc[r*4+b]);
                    acc[r*4+b] = fmaf(wv[r].w, hv.w, acc[r*4+b]);
                }
            }
        }
        float part = multi_reduce32(acc, l);
        red[w*32 + l] = part;
        __syncthreads();
        if (tid < 32) {
            float sum = bgv;
#pragma unroll
            for (int ww = 0; ww < 8; ww++) sum += red[ww*32 + tid];
            float sig = 1.f / (1.f + __expf(-sum));
            size_t base = ((size_t)bout * SEQ + t) * DMODEL + jout;
            hprev = z[base] * sig + gm[base] * hprev;
            hs[base] = hprev;
            __threadfence();
        }
        __syncthreads();
        if (tid == 0) {
            unsigned sv = *(volatile unsigned*)&g_bar_sense;
            unsigned prev = atomicAdd(&g_bar_count, 1u);
            if (prev == REC_CTAS - 1) {
                g_bar_count = 0;
                __threadfence();
                atomicExch(&g_bar_sense, sv ^ 1u);
            } else {
                while (*(volatile unsigned*)&g_bar_sense == sv) { }
            }
            __threadfence();
        }
        __syncthreads();
    }
}

__device__ void attn_body(
    const float* __restrict__ q, const float* __restrict__ k,
    const float* __restrict__ v, __half* __restrict__ aoh,
    int abid, float (*Qs)[64], float* Ts)
{
    const int qb = abid & 127;
    const int bh = abid >> 7;
    const int b = bh >> 4, h = bh & 15;
    const int tid = threadIdx.x, w = tid >> 5, l = tid & 31;
    const size_t bbase = (size_t)b * SEQ * DMODEL + (size_t)h * 64;
    const int qrow0 = qb * 8;

    const int pr_r  = tid >> 4;
    const int pr_c4 = (tid & 15) * 4;

    if (tid < 128) {
        int r = tid >> 4, c4 = (tid & 15) * 4;
        float4 t = *(const float4*)(q + bbase + (size_t)(qrow0 + r) * DMODEL + c4);
        *(float4*)&Qs[r][c4] = t;
    }

    float4 pf[4];
#pragma unroll
    for (int it = 0; it < 4; it++)
        pf[it] = *(const float4*)(k + bbase + (size_t)(pr_r + it*16) * DMODEL + pr_c4);

    __syncthreads();
    float4 qreg[16];
#pragma unroll
    for (int i = 0; i < 16; i++) qreg[i] = *(const float4*)&Qs[w][i*4];

    float p[32];
#pragma unroll 1
    for (int j = 0; j < 16; j++) {
        __syncthreads();
#pragma unroll
        for (int it = 0; it < 4; it++)
            *(float4*)&Ts[(pr_r + it*16)*AT_TS + pr_c4] = pf[it];
        __syncthreads();
        if (j < 15) {
#pragma unroll
            for (int it = 0; it < 4; it++)
                pf[it] = *(const float4*)(k + bbase + (size_t)((j+1)*64 + pr_r + it*16) * DMODEL + pr_c4);
        }
#pragma unroll
        for (int ii = 0; ii < 2; ii++) {
            const int kr = l + 32*ii;
            const float4* trow = (const float4*)&Ts[kr*AT_TS];
            float s = 0.f;
#pragma unroll
            for (int i = 0; i < 16; i++) {
                float4 tv = trow[i];
                s = fmaf(qreg[i].x, tv.x, s);
                s = fmaf(qreg[i].y, tv.y, s);
                s = fmaf(qreg[i].z, tv.z, s);
                s = fmaf(qreg[i].w, tv.w, s);
            }
            p[2*j + ii] = s * 0.125f;
        }
    }

#pragma unroll
    for (int it = 0; it < 4; it++)
        pf[it] = *(const float4*)(v + bbase + (size_t)(pr_r + it*16) * DMODEL + pr_c4);

    float m = -3.0e38f;
#pragma unroll
    for (int i = 0; i < 32; i++) m = fmaxf(m, p[i]);
#pragma unroll
    for (int o = 16; o; o >>= 1) m = fmaxf(m, __shfl_xor_sync(0xffffffffu, m, o));
    float s = 0.f;
#pragma unroll
    for (int i = 0; i < 32; i++) { p[i] = __expf(p[i] - m); s += p[i]; }
#pragma unroll
    for (int o = 16; o; o >>= 1) s += __shfl_xor_sync(0xffffffffu, s, o);
    float inv = 1.f / s;
#pragma unroll
    for (int i = 0; i < 32; i++) p[i] *= inv;

    float o0[32], o1[32];
#pragma unroll
    for (int i = 0; i < 32; i++) { o0[i] = 0.f; o1[i] = 0.f; }
#pragma unroll 1
    for (int j = 0; j < 16; j++) {
        __syncthreads();
#pragma unroll
        for (int it = 0; it < 4; it++)
            *(float4*)&Ts[(pr_r + it*16)*AT_TS + pr_c4] = pf[it];
        __syncthreads();
        if (j < 15) {
#pragma unroll
            for (int it = 0; it < 4; it++)
                pf[it] = *(const float4*)(v + bbase + (size_t)((j+1)*64 + pr_r + it*16) * DMODEL + pr_c4);
        }
#pragma unroll
        for (int ii = 0; ii < 2; ii++) {
            const int kr = l + 32*ii;
            const float pi = p[2*j + ii];
            const float4* trow = (const float4*)&Ts[kr*AT_TS];
#pragma unroll
            for (int d4 = 0; d4 < 8; d4++) {
                float4 tv = trow[d4];
                o0[d4*4+0] = fmaf(pi, tv.x, o0[d4*4+0]);
                o0[d4*4+1] = fmaf(pi, tv.y, o0[d4*4+1]);
                o0[d4*4+2] = fmaf(pi, tv.z, o0[d4*4+2]);
                o0[d4*4+3] = fmaf(pi, tv.w, o0[d4*4+3]);
            }
#pragma unroll
            for (int d4 = 0; d4 < 8; d4++) {
                float4 tv = trow[8 + d4];
                o1[d4*4+0] = fmaf(pi, tv.x, o1[d4*4+0]);
                o1[d4*4+1] = fmaf(pi, tv.y, o1[d4*4+1]);
                o1[d4*4+2] = fmaf(pi, tv.z, o1[d4*4+2]);
                o1[d4*4+3] = fmaf(pi, tv.w, o1[d4*4+3]);
            }
        }
    }
    float r0 = multi_reduce32(o0, l);
    float r1 = multi_reduce32(o1, l);
    size_t ob = bbase + (size_t)(qrow0 + w) * DMODEL;
    aoh[ob + l]      = __float2half_rn(r0);
    aoh[ob + 32 + l] = __float2half_rn(r1);
}

__global__ __launch_bounds__(256)
void rec_attn_kernel(
    const float* __restrict__ z, const float* __restrict__ gm,
    const float* __restrict__ Wg, const float* __restrict__ bg,
    float* __restrict__ hs,
    const float* __restrict__ q, const float* __restrict__ k,
    const float* __restrict__ v, __half* __restrict__ aoh)
{
    __shared__ float red[256];
    __shared__ float Qs[8][64];
    __shared__ float Ts[64*AT_TS];
    if (blockIdx.x < REC_CTAS) {
        recurrence_body(z, gm, Wg, bg, hs, red);
    } else {
        attn_body(q, k, v, aoh, blockIdx.x - REC_CTAS, Qs, Ts);
    }
}

extern "C" void kernel_launch(void* const* d_in, const int* in_sizes, int n_in,
                              void* d_out, int out_size)
{
    (void)in_sizes; (void)n_in; (void)out_size;
    const float* x   = (const float*)d_in[0];
    const float* n1w = (const float*)d_in[1];
    const float* Wq  = (const float*)d_in[2];  const float* bq = (const float*)d_in[3];
    const float* Wk  = (const float*)d_in[4];  const float* bk = (const float*)d_in[5];
    const float* Wv  = (const float*)d_in[6];  const float* bv = (const float*)d_in[7];
    const float* Wz  = (const float*)d_in[8];  const float* bz = (const float*)d_in[9];
    const float* Wg  = (const float*)d_in[10]; const float* bg = (const float*)d_in[11];
    const float* gdw = (const float*)d_in[12]; const float* gdb= (const float*)d_in[13];
    const float* guw = (const float*)d_in[14]; const float* gub= (const float*)d_in[15];
    const float* Wo  = (const float*)d_in[16]; const float* bo = (const float*)d_in[17];
    const float* n2w = (const float*)d_in[18];
    const float* f1w = (const float*)d_in[19]; const float* f1b= (const float*)d_in[20];
    const float* f2w = (const float*)d_in[21]; const float* f2b= (const float*)d_in[22];
    float* out = (float*)d_out;

    float *qp, *kp, *vp, *zp, *gmp, *hp, *aop, *yp;
    cudaGetSymbolAddress((void**)&qp,  g_q);
    cudaGetSymbolAddress((void**)&kp,  g_k);
    cudaGetSymbolAddress((void**)&vp,  g_v);
    cudaGetSymbolAddress((void**)&zp,  g_z);
    cudaGetSymbolAddress((void**)&gmp, g_gm);
    cudaGetSymbolAddress((void**)&hp,  g_h);
    cudaGetSymbolAddress((void**)&aop, g_ao);
    cudaGetSymbolAddress((void**)&yp,  g_y);

    __half *xnh, *zh, *t1h, *atth, *ynh, *f1h;
    __half *wqh, *wkh, *wvh, *wzh, *woh, *f1wh, *f2wh, *gdwh, *guwh;
    cudaGetSymbolAddress((void**)&xnh,  g_xn_h);
    cudaGetSymbolAddress((void**)&zh,   g_z_h);
    cudaGetSymbolAddress((void**)&t1h,  g_t1_h);
    cudaGetSymbolAddress((void**)&atth, g_att_h);
    cudaGetSymbolAddress((void**)&ynh,  g_yn_h);
    cudaGetSymbolAddress((void**)&f1h,  g_f1_h);
    cudaGetSymbolAddress((void**)&wqh,  g_wq_h);
    cudaGetSymbolAddress((void**)&wkh,  g_wk_h);
    cudaGetSymbolAddress((void**)&wvh,  g_wv_h);
    cudaGetSymbolAddress((void**)&wzh,  g_wz_h);
    cudaGetSymbolAddress((void**)&woh,  g_wo_h);
    cudaGetSymbolAddress((void**)&f1wh, g_f1w_h);
    cudaGetSymbolAddress((void**)&f2wh, g_f2w_h);
    cudaGetSymbolAddress((void**)&gdwh, g_gdw_h);
    cudaGetSymbolAddress((void**)&guwh, g_guw_h);

    cudaFuncSetAttribute(hgemm_kernel<0>, cudaFuncAttributeMaxDynamicSharedMemorySize, HG_SMEM_BYTES);
    cudaFuncSetAttribute(hgemm_kernel<1>, cudaFuncAttributeMaxDynamicSharedMemorySize, HG_SMEM_BYTES);
    cudaFuncSetAttribute(hgemm_kernel<2>, cudaFuncAttributeMaxDynamicSharedMemorySize, HG_SMEM_BYTES);
    cudaFuncSetAttribute(hgemm_kernel<3>, cudaFuncAttributeMaxDynamicSharedMemorySize, HG_SMEM_BYTES);
    cudaFuncSetAttribute(hgemm4_kernel,   cudaFuncAttributeMaxDynamicSharedMemorySize, HG_SMEM_BYTES);

    // 0. weight conversion (f32 -> f16)
    CJobs jobs;
    jobs.j[0] = {Wq,  wqh,  DMODEL*DMODEL};
    jobs.j[1] = {Wk,  wkh,  DMODEL*DMODEL};
    jobs.j[2] = {Wv,  wvh,  DMODEL*DMODEL};
    jobs.j[3] = {Wz,  wzh,  DMODEL*DMODEL};
    jobs.j[4] = {Wo,  woh,  DMODEL*DMODEL};
    jobs.j[5] = {f1w, f1wh, FFDIM*DMODEL};
    jobs.j[6] = {f2w, f2wh, DMODEL*FFDIM};
    jobs.j[7] = {gdw, gdwh, 128*DMODEL};
    jobs.j[8] = {guw, guwh, DMODEL*128};
    cvt_kernel<<<dim3(1024, 9), 256>>>(jobs);

    // 1. rmsnorm -> fp16
    rmsnorm_kernel<<<NTOK, 256>>>(x, n1w, xnh);
    // 2. Q/K/V/Z projections (fp16 mma), fused; z gets both f32 + f16
    HQuad quad;
    quad.p[0] = {wqh, bq, qp, nullptr};
    quad.p[1] = {wkh, bk, kp, nullptr};
    quad.p[2] = {wvh, bv, vp, nullptr};
    quad.p[3] = {wzh, bz, zp, zh};
    hgemm4_kernel<<<dim3(DMODEL/128, NTOK/128, 4), 256, HG_SMEM_BYTES>>>(xnh, quad, DMODEL, DMODEL);
    // 3. gamma MLP
    hgemm_kernel<1><<<dim3(1, NTOK/128), 256, HG_SMEM_BYTES>>>(zh, gdwh, gdb, nullptr, nullptr, t1h, 128, DMODEL);
    hgemm_kernel<2><<<dim3(DMODEL/128, NTOK/128), 256, HG_SMEM_BYTES>>>(t1h, guwh, gub, nullptr, gmp, nullptr, DMODEL, 128);
    // 4+5a. recurrence + attention, overlapped
    rec_attn_kernel<<<REC_CTAS + 4*16*128, 256>>>(zp, gmp, Wg, bg, hp, qp, kp, vp, atth);
    // 5b. Wo projection
    hgemm_kernel<0><<<dim3(DMODEL/128, NTOK/128), 256, HG_SMEM_BYTES>>>(atth, woh, bo, nullptr, aop, nullptr, DMODEL, DMODEL);
    // 6-7. residual + norm2, FFN, final residual (-> d_out)
    residual_norm_kernel<<<NTOK, 256>>>(x, aop, hp, n2w, yp, ynh);
    hgemm_kernel<3><<<dim3(FFDIM/128, NTOK/128), 256, HG_SMEM_BYTES>>>(ynh, f1wh, f1b, nullptr, nullptr, f1h, FFDIM, DMODEL);
    hgemm_kernel<0><<<dim3(DMODEL/128, NTOK/128), 256, HG_SMEM_BYTES>>>(f1h, f2wh, f2b, yp, out, nullptr, DMODEL, FFDIM);
}

// round 17
// speedup vs baseline: 1.3141x; 1.0070x over previous
#include <cuda_runtime.h>
#include <cuda_fp16.h>
#include <cstddef>
#include <cstdint>
#include <math.h>

#define DMODEL 1024
#define NTOK   4096
#define FFDIM  4096
#define SEQ    1024
#define REC_CTAS 128

// f32 scratch
__device__ float g_q  [NTOK*DMODEL];
__device__ float g_k  [NTOK*DMODEL];
__device__ float g_v  [NTOK*DMODEL];
__device__ float g_z  [NTOK*DMODEL];
__device__ float g_gm [NTOK*DMODEL];
__device__ float g_h  [NTOK*DMODEL];
__device__ float g_ao [NTOK*DMODEL];
__device__ float g_y  [NTOK*DMODEL];
__device__ unsigned g_bar_count;
__device__ unsigned g_bar_sense;

// fp16 scratch (activations + converted weights)
__device__ __align__(16) __half g_xn_h [NTOK*DMODEL];
__device__ __align__(16) __half g_z_h  [NTOK*DMODEL];
__device__ __align__(16) __half g_t1_h [NTOK*128];
__device__ __align__(16) __half g_att_h[NTOK*DMODEL];
__device__ __align__(16) __half g_yn_h [NTOK*DMODEL];
__device__ __align__(16) __half g_f1_h [NTOK*FFDIM];
__device__ __align__(16) __half g_wq_h [DMODEL*DMODEL];
__device__ __align__(16) __half g_wk_h [DMODEL*DMODEL];
__device__ __align__(16) __half g_wv_h [DMODEL*DMODEL];
__device__ __align__(16) __half g_wz_h [DMODEL*DMODEL];
__device__ __align__(16) __half g_wo_h [DMODEL*DMODEL];
__device__ __align__(16) __half g_f1w_h[FFDIM*DMODEL];
__device__ __align__(16) __half g_f2w_h[DMODEL*FFDIM];
__device__ __align__(16) __half g_gdw_h[128*DMODEL];
__device__ __align__(16) __half g_guw_h[DMODEL*128];

// ---------------- helpers ----------------
__device__ __forceinline__ void mma_f16(float* c,
    unsigned a0, unsigned a1, unsigned a2, unsigned a3,
    unsigned b0, unsigned b1)
{
    asm volatile("mma.sync.aligned.m16n8k16.row.col.f32.f16.f16.f32 "
                 "{%0,%1,%2,%3}, {%4,%5,%6,%7}, {%8,%9}, {%0,%1,%2,%3};\n"
                 : "+f"(c[0]), "+f"(c[1]), "+f"(c[2]), "+f"(c[3])
                 : "r"(a0), "r"(a1), "r"(a2), "r"(a3), "r"(b0), "r"(b1));
}

__device__ __forceinline__ void cp_async16(uint32_t dst_smem, const void* src) {
    asm volatile("cp.async.cg.shared.global [%0], [%1], 16;"
                 :: "r"(dst_smem), "l"(src));
}
__device__ __forceinline__ void cp_commit() {
    asm volatile("cp.async.commit_group;");
}

__device__ __forceinline__ float multi_reduce32(float (&acc)[32], int lane) {
#pragma unroll
    for (int d = 16; d >= 1; d >>= 1) {
        const bool up = (lane & d) != 0;
#pragma unroll
        for (int i = 0; i < d; i++) {
            float send = up ? acc[i] : acc[i + d];
            float recv = __shfl_xor_sync(0xffffffffu, send, d);
            float keep = up ? acc[i + d] : acc[i];
            acc[i] = keep + recv;
        }
    }
    return acc[0];
}

__device__ __forceinline__ float block_sum256(float v) {
    __shared__ float sred[9];
#pragma unroll
    for (int o = 16; o; o >>= 1) v += __shfl_xor_sync(0xffffffffu, v, o);
    int w = threadIdx.x >> 5, l = threadIdx.x & 31;
    if (l == 0) sred[w] = v;
    __syncthreads();
    if (threadIdx.x < 32) {
        float t = (l < 8) ? sred[l] : 0.f;
#pragma unroll
        for (int o = 4; o; o >>= 1) t += __shfl_xor_sync(0xffffffffu, t, o);
        if (l == 0) sred[8] = t;
    }
    __syncthreads();
    return sred[8];
}

// weight f32 -> f16 conversion (runs every launch; deterministic)
struct CJob { const float* s; __half* d; int n; };
struct CJobs { CJob j[9]; };
__global__ __launch_bounds__(256)
void cvt_kernel(CJobs jobs) {
    CJob job = jobs.j[blockIdx.y];
    const int nh = job.n >> 1;
    const int stride = gridDim.x * blockDim.x;
    for (int i = blockIdx.x * blockDim.x + threadIdx.x; i < nh; i += stride) {
        float2 f = ((const float2*)job.s)[i];
        ((__half2*)job.d)[i] = __floats2half2_rn(f.x, f.y);
    }
}

__global__ __launch_bounds__(256)
void rmsnorm_kernel(const float* __restrict__ x, const float* __restrict__ w,
                    __half* __restrict__ outh) {
    const size_t base = (size_t)blockIdx.x * DMODEL;
    float vb[4]; float ss = 0.f;
#pragma unroll
    for (int i = 0; i < 4; i++) { float t = x[base + threadIdx.x + 256*i]; vb[i] = t; ss += t*t; }
    float inv = 1.f / (sqrtf(block_sum256(ss)) * 0.03125f + 1e-6f);
#pragma unroll
    for (int i = 0; i < 4; i++) {
        int c = threadIdx.x + 256*i;
        outh[base + c] = __float2half_rn(w[c] * vb[i] * inv);
    }
}

__global__ __launch_bounds__(256)
void residual_norm_kernel(const float* __restrict__ x, const float* __restrict__ ao,
                          const float* __restrict__ hs, const float* __restrict__ w,
                          float* __restrict__ y, __half* __restrict__ ynh) {
    const size_t base = (size_t)blockIdx.x * DMODEL;
    float vb[4]; float ss = 0.f;
#pragma unroll
    for (int i = 0; i < 4; i++) {
        int c = threadIdx.x + 256*i;
        float t = x[base+c] + ao[base+c] + hs[base+c];
        vb[i] = t; y[base+c] = t; ss += t*t;
    }
    float inv = 1.f / (sqrtf(block_sum256(ss)) * 0.03125f + 1e-6f);
#pragma unroll
    for (int i = 0; i < 4; i++) {
        int c = threadIdx.x + 256*i;
        ynh[base + c] = __float2half_rn(w[c] * vb[i] * inv);
    }
}

// ---------------- FP16 tensor-core GEMM (m16n8k16, BK=64, 3-stage ring) -------
// C[M,N] = A[M,K] @ B[N,K]^T + bias. A,B fp16; accum f32. Block 128x128.
// SMEM: 128B rows (8 x 16B chunks), swizzle chunk c ^ (r&7) -> conflict-free.
#define HG_BK    64
#define HG_STAGE 16384
#define HG_SMEM_BYTES (6*HG_STAGE)

template<int EPI>
__device__ __forceinline__
void hgemm_body(const __half* __restrict__ A, const __half* __restrict__ B,
                const float* __restrict__ bias, const float* __restrict__ res,
                float* __restrict__ Cf, __half* __restrict__ Ch,
                int N, int K, char* hsm, int bm, int bn)
{
    const int tid = threadIdx.x;
    const int wid = tid >> 5, lane = tid & 31;
    const int gq = lane >> 2, tq = lane & 3;
    const int m0 = (wid & 1) * 64, n0 = (wid >> 1) * 32;

    const int frow = tid >> 1;                 // fill row
    const int fc0  = (tid & 1) * 4;            // first of 4 chunks this thread fills
    const __half* Ap = A + (size_t)(bm + frow) * K + fc0 * 8;
    const __half* Bp = B + (size_t)(bn + frow) * K + fc0 * 8;

    const uint32_t base = (uint32_t)__cvta_generic_to_shared(hsm);
    uint32_t off[4];
#pragma unroll
    for (int c = 0; c < 4; c++)
        off[c] = frow * 128u + (uint32_t)(((fc0 + c) ^ (frow & 7)) << 4);

    float acc[4][4][4];
#pragma unroll
    for (int i = 0; i < 4; i++)
#pragma unroll
        for (int j = 0; j < 4; j++)
#pragma unroll
            for (int e = 0; e < 4; e++) acc[i][j][e] = 0.f;

    const int NC = K / HG_BK;

    // fill stage st with k-tile t (4 x 16B per operand per thread)
    // (lambda-free for ptxas friendliness)
#define HG_FILL(st, t) do {                                                     \
        const __half* Aq = Ap + (size_t)(t) * HG_BK;                            \
        const __half* Bq = Bp + (size_t)(t) * HG_BK;                            \
        _Pragma("unroll")                                                       \
        for (int c = 0; c < 4; c++) {                                           \
            cp_async16(base + (st)*HG_STAGE + off[c], Aq + c*8);                \
            cp_async16(base + 3*HG_STAGE + (st)*HG_STAGE + off[c], Bq + c*8);   \
        }                                                                       \
    } while (0)

    HG_FILL(0, 0);
    cp_commit();
    if (NC > 1) HG_FILL(1, 1);
    cp_commit();

    int s = 0, s2 = 2;
    for (int t = 0; t < NC; t++) {
        asm volatile("cp.async.wait_group 1;");
        __syncthreads();
        if (t + 2 < NC) HG_FILL(s2, t + 2);
        cp_commit();

        const char* Ab = hsm + s * HG_STAGE;
        const char* Bb = hsm + 3 * HG_STAGE + s * HG_STAGE;
#pragma unroll
        for (int ks = 0; ks < 4; ks++) {
            unsigned bf[4][2];
#pragma unroll
            for (int j = 0; j < 4; j++) {
                const int n = n0 + j*8 + gq;
                const int sw = n & 7;
                bf[j][0] = *(const uint32_t*)(Bb + n*128 + (((2*ks  ) ^ sw) << 4) + 4*tq);
                bf[j][1] = *(const uint32_t*)(Bb + n*128 + (((2*ks+1) ^ sw) << 4) + 4*tq);
            }
#pragma unroll
            for (int i = 0; i < 4; i++) {
                const int r = m0 + i*16 + gq;
                const int sw = r & 7;          // same for r and r+8
                const int c0off = (((2*ks  ) ^ sw) << 4) + 4*tq;
                const int c1off = (((2*ks+1) ^ sw) << 4) + 4*tq;
                unsigned a0 = *(const uint32_t*)(Ab + r*128 + c0off);
                unsigned a1 = *(const uint32_t*)(Ab + (r+8)*128 + c0off);
                unsigned a2 = *(const uint32_t*)(Ab + r*128 + c1off);
                unsigned a3 = *(const uint32_t*)(Ab + (r+8)*128 + c1off);
#pragma unroll
                for (int j = 0; j < 4; j++)
                    mma_f16(acc[i][j], a0, a1, a2, a3, bf[j][0], bf[j][1]);
            }
        }
        s  = (s  == 2) ? 0 : s  + 1;
        s2 = (s2 == 2) ? 0 : s2 + 1;
    }
#undef HG_FILL

#pragma unroll
    for (int i = 0; i < 4; i++) {
#pragma unroll
        for (int half = 0; half < 2; half++) {
            const int gr = bm + m0 + i*16 + gq + half*8;
            float* cfr = Cf ? Cf + (size_t)gr * N : nullptr;
            __half* chr = Ch ? Ch + (size_t)gr * N : nullptr;
            const float* rrow = res ? res + (size_t)gr * N : nullptr;
#pragma unroll
            for (int j = 0; j < 4; j++) {
                const int gc = bn + n0 + j*8 + tq*2;
                float vv2[2];
#pragma unroll
                for (int e = 0; e < 2; e++) {
                    float vv = acc[i][j][half*2 + e] + bias[gc + e];
                    if (EPI == 1) vv = fmaxf(vv, 0.f);
                    else if (EPI == 2) {
                        vv = 1.f / (1.f + __expf(-vv));
                        vv = fminf(fmaxf(vv, 1e-6f), 1.f - 1e-6f);
                    } else if (EPI == 3) {
                        float u = 0.7978845608028654f * (vv + 0.044715f * vv * vv * vv);
                        vv = 0.5f * vv * (1.f + tanhf(u));
                    }
                    if (rrow) vv += rrow[gc + e];
                    vv2[e] = vv;
                }
                if (cfr) { cfr[gc] = vv2[0]; cfr[gc + 1] = vv2[1]; }
                if (chr) *(__half2*)(chr + gc) = __floats2half2_rn(vv2[0], vv2[1]);
            }
        }
    }
}

template<int EPI>
__global__ __launch_bounds__(256, 2)
void hgemm_kernel(const __half* __restrict__ A, const __half* __restrict__ B,
                  const float* __restrict__ bias, const float* __restrict__ res,
                  float* __restrict__ Cf, __half* __restrict__ Ch, int N, int K)
{
    extern __shared__ char hsm[];
    hgemm_body<EPI>(A, B, bias, res, Cf, Ch, N, K, hsm,
                    blockIdx.y * 128, blockIdx.x * 128);
}

struct HPtr { const __half* B; const float* bias; float* Cf; __half* Ch; };
struct HQuad { HPtr p[4]; };

__global__ __launch_bounds__(256, 2)
void hgemm4_kernel(const __half* __restrict__ A, HQuad q, int N, int K)
{
    extern __shared__ char hsm[];
    HPtr pr = q.p[blockIdx.z];
    hgemm_body<0>(A, pr.B, pr.bias, nullptr, pr.Cf, pr.Ch, N, K, hsm,
                  blockIdx.y * 128, blockIdx.x * 128);
}

// ================= merged recurrence + attention (R14 winner) =================
#define AT_TS 68

__device__ void recurrence_body(
    const float* __restrict__ z, const float* __restrict__ gm,
    const float* __restrict__ Wg, const float* __restrict__ bg,
    float* __restrict__ hs, float* red)
{
    const int tid = threadIdx.x, w = tid >> 5, l = tid & 31;
    const int blk = blockIdx.x;
    const int k0 = w * 128 + l * 4;
    float4 wv[8];
#pragma unroll
    for (int r = 0; r < 8; r++)
        wv[r] = *(const float4*)(Wg + (size_t)(blk*8 + r) * DMODEL + k0);

    float bgv = 0.f, hprev = 0.f; int jout = 0, bout = 0;
    if (tid < 32) { jout = blk*8 + (tid >> 2); bout = tid & 3; bgv = bg[jout]; }

    for (int t = 0; t < SEQ; t++) {
        float acc[32];
#pragma unroll
        for (int a = 0; a < 32; a++) acc[a] = 0.f;
        if (t > 0) {
#pragma unroll
            for (int b = 0; b < 4; b++) {
                float4 hv = __ldcg((const float4*)(hs + ((size_t)b*SEQ + (t-1))*DMODEL + k0));
#pragma unroll
                for (int r = 0; r < 8; r++) {
                    acc[r*4+b] = fmaf(wv[r].x, hv.x, acc[r*4+b]);
                    acc[r*4+b] = fmaf(wv[r].y, hv.y, acc[r*4+b]);
                    acc[r*4+b] = fmaf(wv[r].z, hv.z, acc[r*4+b]);
                    acc[r*4+b] = fmaf(wv[r].w, hv.w, acc[r*4+b]);
                }
            }
        }
        float part = multi_reduce32(acc, l);
        red[w*32 + l] = part;
        __syncthreads();
        if (tid < 32) {
            float sum = bgv;
#pragma unroll
            for (int ww = 0; ww < 8; ww++) sum += red[ww*32 + tid];
            float sig = 1.f / (1.f + __expf(-sum));
            size_t base = ((size_t)bout * SEQ + t) * DMODEL + jout;
            hprev = z[base] * sig + gm[base] * hprev;
            hs[base] = hprev;
            __threadfence();
        }
        __syncthreads();
        if (tid == 0) {
            unsigned sv = *(volatile unsigned*)&g_bar_sense;
            unsigned prev = atomicAdd(&g_bar_count, 1u);
            if (prev == REC_CTAS - 1) {
                g_bar_count = 0;
                __threadfence();
                atomicExch(&g_bar_sense, sv ^ 1u);
            } else {
                while (*(volatile unsigned*)&g_bar_sense == sv) { }
            }
            __threadfence();
        }
        __syncthreads();
    }
}

__device__ void attn_body(
    const float* __restrict__ q, const float* __restrict__ k,
    const float* __restrict__ v, __half* __restrict__ aoh,
    int abid, float (*Qs)[64], float* Ts)
{
    const int qb = abid & 127;
    const int bh = abid >> 7;
    const int b = bh >> 4, h = bh & 15;
    const int tid = threadIdx.x, w = tid >> 5, l = tid & 31;
    const size_t bbase = (size_t)b * SEQ * DMODEL + (size_t)h * 64;
    const int qrow0 = qb * 8;

    const int pr_r  = tid >> 4;
    const int pr_c4 = (tid & 15) * 4;

    if (tid < 128) {
        int r = tid >> 4, c4 = (tid & 15) * 4;
        float4 t = *(const float4*)(q + bbase + (size_t)(qrow0 + r) * DMODEL + c4);
        *(float4*)&Qs[r][c4] = t;
    }

    float4 pf[4];
#pragma unroll
    for (int it = 0; it < 4; it++)
        pf[it] = *(const float4*)(k + bbase + (size_t)(pr_r + it*16) * DMODEL + pr_c4);

    __syncthreads();
    float4 qreg[16];
#pragma unroll
    for (int i = 0; i < 16; i++) qreg[i] = *(const float4*)&Qs[w][i*4];

    float p[32];
#pragma unroll 1
    for (int j = 0; j < 16; j++) {
        __syncthreads();
#pragma unroll
        for (int it = 0; it < 4; it++)
            *(float4*)&Ts[(pr_r + it*16)*AT_TS + pr_c4] = pf[it];
        __syncthreads();
        if (j < 15) {
#pragma unroll
            for (int it = 0; it < 4; it++)
                pf[it] = *(const float4*)(k + bbase + (size_t)((j+1)*64 + pr_r + it*16) * DMODEL + pr_c4);
        }
#pragma unroll
        for (int ii = 0; ii < 2; ii++) {
            const int kr = l + 32*ii;
            const float4* trow = (const float4*)&Ts[kr*AT_TS];
            float s = 0.f;
#pragma unroll
            for (int i = 0; i < 16; i++) {
                float4 tv = trow[i];
                s = fmaf(qreg[i].x, tv.x, s);
                s = fmaf(qreg[i].y, tv.y, s);
                s = fmaf(qreg[i].z, tv.z, s);
                s = fmaf(qreg[i].w, tv.w, s);
            }
            p[2*j + ii] = s * 0.125f;
        }
    }

#pragma unroll
    for (int it = 0; it < 4; it++)
        pf[it] = *(const float4*)(v + bbase + (size_t)(pr_r + it*16) * DMODEL + pr_c4);

    float m = -3.0e38f;
#pragma unroll
    for (int i = 0; i < 32; i++) m = fmaxf(m, p[i]);
#pragma unroll
    for (int o = 16; o; o >>= 1) m = fmaxf(m, __shfl_xor_sync(0xffffffffu, m, o));
    float s = 0.f;
#pragma unroll
    for (int i = 0; i < 32; i++) { p[i] = __expf(p[i] - m); s += p[i]; }
#pragma unroll
    for (int o = 16; o; o >>= 1) s += __shfl_xor_sync(0xffffffffu, s, o);
    float inv = 1.f / s;
#pragma unroll
    for (int i = 0; i < 32; i++) p[i] *= inv;

    float o0[32], o1[32];
#pragma unroll
    for (int i = 0; i < 32; i++) { o0[i] = 0.f; o1[i] = 0.f; }
#pragma unroll 1
    for (int j = 0; j < 16; j++) {
        __syncthreads();
#pragma unroll
        for (int it = 0; it < 4; it++)
            *(float4*)&Ts[(pr_r + it*16)*AT_TS + pr_c4] = pf[it];
        __syncthreads();
        if (j < 15) {
#pragma unroll
            for (int it = 0; it < 4; it++)
                pf[it] = *(const float4*)(v + bbase + (size_t)((j+1)*64 + pr_r + it*16) * DMODEL + pr_c4);
        }
#pragma unroll
        for (int ii = 0; ii < 2; ii++) {
            const int kr = l + 32*ii;
            const float pi = p[2*j + ii];
            const float4* trow = (const float4*)&Ts[kr*AT_TS];
#pragma unroll
            for (int d4 = 0; d4 < 8; d4++) {
                float4 tv = trow[d4];
                o0[d4*4+0] = fmaf(pi, tv.x, o0[d4*4+0]);
                o0[d4*4+1] = fmaf(pi, tv.y, o0[d4*4+1]);
                o0[d4*4+2] = fmaf(pi, tv.z, o0[d4*4+2]);
                o0[d4*4+3] = fmaf(pi, tv.w, o0[d4*4+3]);
            }
#pragma unroll
            for (int d4 = 0; d4 < 8; d4++) {
                float4 tv = trow[8 + d4];
                o1[d4*4+0] = fmaf(pi, tv.x, o1[d4*4+0]);
                o1[d4*4+1] = fmaf(pi, tv.y, o1[d4*4+1]);
                o1[d4*4+2] = fmaf(pi, tv.z, o1[d4*4+2]);
                o1[d4*4+3] = fmaf(pi, tv.w, o1[d4*4+3]);
            }
        }
    }
    float r0 = multi_reduce32(o0, l);
    float r1 = multi_reduce32(o1, l);
    size_t ob = bbase + (size_t)(qrow0 + w) * DMODEL;
    aoh[ob + l]      = __float2half_rn(r0);
    aoh[ob + 32 + l] = __float2half_rn(r1);
}

__global__ __launch_bounds__(256)
void rec_attn_kernel(
    const float* __restrict__ z, const float* __restrict__ gm,
    const float* __restrict__ Wg, const float* __restrict__ bg,
    float* __restrict__ hs,
    const float* __restrict__ q, const float* __restrict__ k,
    const float* __restrict__ v, __half* __restrict__ aoh)
{
    __shared__ float red[256];
    __shared__ float Qs[8][64];
    __shared__ float Ts[64*AT_TS];
    if (blockIdx.x < REC_CTAS) {
        recurrence_body(z, gm, Wg, bg, hs, red);
    } else {
        attn_body(q, k, v, aoh, blockIdx.x - REC_CTAS, Qs, Ts);
    }
}

extern "C" void kernel_launch(void* const* d_in, const int* in_sizes, int n_in,
                              void* d_out, int out_size)
{
    (void)in_sizes; (void)n_in; (void)out_size;
    const float* x   = (const float*)d_in[0];
    const float* n1w = (const float*)d_in[1];
    const float* Wq  = (const float*)d_in[2];  const float* bq = (const float*)d_in[3];
    const float* Wk  = (const float*)d_in[4];  const float* bk = (const float*)d_in[5];
    const float* Wv  = (const float*)d_in[6];  const float* bv = (const float*)d_in[7];
    const float* Wz  = (const float*)d_in[8];  const float* bz = (const float*)d_in[9];
    const float* Wg  = (const float*)d_in[10]; const float* bg = (const float*)d_in[11];
    const float* gdw = (const float*)d_in[12]; const float* gdb= (const float*)d_in[13];
    const float* guw = (const float*)d_in[14]; const float* gub= (const float*)d_in[15];
    const float* Wo  = (const float*)d_in[16]; const float* bo = (const float*)d_in[17];
    const float* n2w = (const float*)d_in[18];
    const float* f1w = (const float*)d_in[19]; const float* f1b= (const float*)d_in[20];
    const float* f2w = (const float*)d_in[21]; const float* f2b= (const float*)d_in[22];
    float* out = (float*)d_out;

    float *qp, *kp, *vp, *zp, *gmp, *hp, *aop, *yp;
    cudaGetSymbolAddress((void**)&qp,  g_q);
    cudaGetSymbolAddress((void**)&kp,  g_k);
    cudaGetSymbolAddress((void**)&vp,  g_v);
    cudaGetSymbolAddress((void**)&zp,  g_z);
    cudaGetSymbolAddress((void**)&gmp, g_gm);
    cudaGetSymbolAddress((void**)&hp,  g_h);
    cudaGetSymbolAddress((void**)&aop, g_ao);
    cudaGetSymbolAddress((void**)&yp,  g_y);

    __half *xnh, *zh, *t1h, *atth, *ynh, *f1h;
    __half *wqh, *wkh, *wvh, *wzh, *woh, *f1wh, *f2wh, *gdwh, *guwh;
    cudaGetSymbolAddress((void**)&xnh,  g_xn_h);
    cudaGetSymbolAddress((void**)&zh,   g_z_h);
    cudaGetSymbolAddress((void**)&t1h,  g_t1_h);
    cudaGetSymbolAddress((void**)&atth, g_att_h);
    cudaGetSymbolAddress((void**)&ynh,  g_yn_h);
    cudaGetSymbolAddress((void**)&f1h,  g_f1_h);
    cudaGetSymbolAddress((void**)&wqh,  g_wq_h);
    cudaGetSymbolAddress((void**)&wkh,  g_wk_h);
    cudaGetSymbolAddress((void**)&wvh,  g_wv_h);
    cudaGetSymbolAddress((void**)&wzh,  g_wz_h);
    cudaGetSymbolAddress((void**)&woh,  g_wo_h);
    cudaGetSymbolAddress((void**)&f1wh, g_f1w_h);
    cudaGetSymbolAddress((void**)&f2wh, g_f2w_h);
    cudaGetSymbolAddress((void**)&gdwh, g_gdw_h);
    cudaGetSymbolAddress((void**)&guwh, g_guw_h);

    cudaFuncSetAttribute(hgemm_kernel<0>, cudaFuncAttributeMaxDynamicSharedMemorySize, HG_SMEM_BYTES);
    cudaFuncSetAttribute(hgemm_kernel<1>, cudaFuncAttributeMaxDynamicSharedMemorySize, HG_SMEM_BYTES);
    cudaFuncSetAttribute(hgemm_kernel<2>, cudaFuncAttributeMaxDynamicSharedMemorySize, HG_SMEM_BYTES);
    cudaFuncSetAttribute(hgemm_kernel<3>, cudaFuncAttributeMaxDynamicSharedMemorySize, HG_SMEM_BYTES);
    cudaFuncSetAttribute(hgemm4_kernel,   cudaFuncAttributeMaxDynamicSharedMemorySize, HG_SMEM_BYTES);

    // 0. weight conversion (f32 -> f16)
    CJobs jobs;
    jobs.j[0] = {Wq,  wqh,  DMODEL*DMODEL};
    jobs.j[1] = {Wk,  wkh,  DMODEL*DMODEL};
    jobs.j[2] = {Wv,  wvh,  DMODEL*DMODEL};
    jobs.j[3] = {Wz,  wzh,  DMODEL*DMODEL};
    jobs.j[4] = {Wo,  woh,  DMODEL*DMODEL};
    jobs.j[5] = {f1w, f1wh, FFDIM*DMODEL};
    jobs.j[6] = {f2w, f2wh, DMODEL*FFDIM};
    jobs.j[7] = {gdw, gdwh, 128*DMODEL};
    jobs.j[8] = {guw, guwh, DMODEL*128};
    cvt_kernel<<<dim3(1024, 9), 256>>>(jobs);

    // 1. rmsnorm -> fp16
    rmsnorm_kernel<<<NTOK, 256>>>(x, n1w, xnh);
    // 2. Q/K/V/Z projections (fp16 mma), fused; z gets both f32 + f16
    HQuad quad;
    quad.p[0] = {wqh, bq, qp, nullptr};
    quad.p[1] = {wkh, bk, kp, nullptr};
    quad.p[2] = {wvh, bv, vp, nullptr};
    quad.p[3] = {wzh, bz, zp, zh};
    hgemm4_kernel<<<dim3(DMODEL/128, NTOK/128, 4), 256, HG_SMEM_BYTES>>>(xnh, quad, DMODEL, DMODEL);
    // 3. gamma MLP
    hgemm_kernel<1><<<dim3(1, NTOK/128), 256, HG_SMEM_BYTES>>>(zh, gdwh, gdb, nullptr, nullptr, t1h, 128, DMODEL);
    hgemm_kernel<2><<<dim3(DMODEL/128, NTOK/128), 256, HG_SMEM_BYTES>>>(t1h, guwh, gub, nullptr, gmp, nullptr, DMODEL, 128);
    // 4+5a. recurrence + attention, overlapped
    rec_attn_kernel<<<REC_CTAS + 4*16*128, 256>>>(zp, gmp, Wg, bg, hp, qp, kp, vp, atth);
    // 5b. Wo projection
    hgemm_kernel<0><<<dim3(DMODEL/128, NTOK/128), 256, HG_SMEM_BYTES>>>(atth, woh, bo, nullptr, aop, nullptr, DMODEL, DMODEL);
    // 6-7. residual + norm2, FFN, final residual (-> d_out)
    residual_norm_kernel<<<NTOK, 256>>>(x, aop, hp, n2w, yp, ynh);
    hgemm_kernel<3><<<dim3(FFDIM/128, NTOK/128), 256, HG_SMEM_BYTES>>>(ynh, f1wh, f1b, nullptr, nullptr, f1h, FFDIM, DMODEL);
    hgemm_kernel<0><<<dim3(DMODEL/128, NTOK/128), 256, HG_SMEM_BYTES>>>(f1h, f2wh, f2b, yp, out, nullptr, DMODEL, FFDIM);
}